// round 1
// baseline (speedup 1.0000x reference)
#include <cuda_runtime.h>
#include <math.h>

#define D_MODEL 1024
#define N_HEADS 16
#define HEAD_DIM 64
#define D_FF     4096
#define BATCH    2
#define SEQ      2048
#define M_TOK    (BATCH*SEQ)   /* 4096 rows of tokens */

// ---------------- scratch (static device globals; no allocation) -------------
__device__ float g_h1 [M_TOK*D_MODEL];
__device__ float g_q  [M_TOK*D_MODEL];
__device__ float g_k  [M_TOK*D_MODEL];
__device__ float g_v  [M_TOK*D_MODEL];
__device__ float g_ctx[M_TOK*D_MODEL];
__device__ float g_x1 [M_TOK*D_MODEL];
__device__ float g_h2 [M_TOK*D_MODEL];
__device__ float g_ff [M_TOK*D_FF];

// ---------------- LayerNorm --------------------------------------------------
__device__ __forceinline__ float block_reduce_sum(float v, float* sh) {
    #pragma unroll
    for (int o = 16; o > 0; o >>= 1) v += __shfl_down_sync(0xFFFFFFFFu, v, o);
    int lane = threadIdx.x & 31, w = threadIdx.x >> 5;
    if (lane == 0) sh[w] = v;
    __syncthreads();
    if (w == 0) {
        v = (lane < 8) ? sh[lane] : 0.0f;
        #pragma unroll
        for (int o = 4; o > 0; o >>= 1) v += __shfl_down_sync(0xFFFFFFFFu, v, o);
        if (lane == 0) sh[0] = v;
    }
    __syncthreads();
    float r = sh[0];
    __syncthreads();
    return r;
}

__global__ void ln_kernel(const float* __restrict__ x,
                          const float* __restrict__ gamma,
                          const float* __restrict__ beta,
                          float* __restrict__ out) {
    __shared__ float sh[32];
    const int row = blockIdx.x;
    const float* xr = x + (size_t)row * D_MODEL;
    float v[4];
    float s = 0.0f;
    #pragma unroll
    for (int i = 0; i < 4; i++) { v[i] = xr[threadIdx.x + i * 256]; s += v[i]; }
    float mean = block_reduce_sum(s, sh) * (1.0f / D_MODEL);
    float s2 = 0.0f;
    #pragma unroll
    for (int i = 0; i < 4; i++) { float d = v[i] - mean; s2 += d * d; }
    float var = block_reduce_sum(s2, sh) * (1.0f / D_MODEL);
    float rstd = rsqrtf(var + 1e-5f);
    float* orow = out + (size_t)row * D_MODEL;
    #pragma unroll
    for (int i = 0; i < 4; i++) {
        int idx = threadIdx.x + i * 256;
        orow[idx] = (v[i] - mean) * rstd * gamma[idx] + beta[idx];
    }
}

// ---------------- Tiled SGEMM:  C[M,N] = A[M,K] @ W[N,K]^T  ------------------
// EPI: 0 = +bias, 1 = +bias then exact GELU, 2 = +bias + residual
// BM=BN=128, BK=8, 256 threads, 8x8 accumulators per thread.
// Requires M%128==0, N%128==0, K%8==0 (all shapes here satisfy this).
template<int EPI>
__global__ void __launch_bounds__(256)
gemm_kernel(const float* __restrict__ A, const float* __restrict__ W,
            const float* __restrict__ bias, const float* __restrict__ res,
            float* __restrict__ C, int M, int N, int K) {
    __shared__ float As[8][128];
    __shared__ float Ws[8][128];

    const int bm = blockIdx.y * 128;
    const int bn = blockIdx.x * 128;
    const int tid = threadIdx.x;
    const int tx = tid & 15;    // 0..15  -> 8 output cols
    const int ty = tid >> 4;    // 0..15  -> 8 output rows

    const int lrow = tid >> 1;         // 0..127
    const int lk4  = (tid & 1) * 4;    // 0 or 4
    const float* Ap = A + (size_t)(bm + lrow) * K + lk4;
    const float* Wp = W + (size_t)(bn + lrow) * K + lk4;

    float acc[8][8];
    #pragma unroll
    for (int i = 0; i < 8; i++)
        #pragma unroll
        for (int j = 0; j < 8; j++) acc[i][j] = 0.0f;

    for (int k0 = 0; k0 < K; k0 += 8) {
        float4 a4 = *(const float4*)(Ap + k0);
        float4 w4 = *(const float4*)(Wp + k0);
        __syncthreads();
        As[lk4 + 0][lrow] = a4.x; As[lk4 + 1][lrow] = a4.y;
        As[lk4 + 2][lrow] = a4.z; As[lk4 + 3][lrow] = a4.w;
        Ws[lk4 + 0][lrow] = w4.x; Ws[lk4 + 1][lrow] = w4.y;
        Ws[lk4 + 2][lrow] = w4.z; Ws[lk4 + 3][lrow] = w4.w;
        __syncthreads();
        #pragma unroll
        for (int kk = 0; kk < 8; kk++) {
            float4 a0 = *(const float4*)&As[kk][ty * 8];
            float4 a1 = *(const float4*)&As[kk][ty * 8 + 4];
            float4 w0 = *(const float4*)&Ws[kk][tx * 8];
            float4 w1 = *(const float4*)&Ws[kk][tx * 8 + 4];
            float a[8] = {a0.x, a0.y, a0.z, a0.w, a1.x, a1.y, a1.z, a1.w};
            float w[8] = {w0.x, w0.y, w0.z, w0.w, w1.x, w1.y, w1.z, w1.w};
            #pragma unroll
            for (int i = 0; i < 8; i++)
                #pragma unroll
                for (int j = 0; j < 8; j++)
                    acc[i][j] = fmaf(a[i], w[j], acc[i][j]);
        }
    }

    #pragma unroll
    for (int i = 0; i < 8; i++) {
        const int row = bm + ty * 8 + i;
        #pragma unroll
        for (int j = 0; j < 8; j++) {
            const int col = bn + tx * 8 + j;
            float v = acc[i][j] + bias[col];
            if (EPI == 1) {
                v = 0.5f * v * (1.0f + erff(v * 0.70710678118654752f));
            } else if (EPI == 2) {
                v += res[(size_t)row * N + col];
            }
            C[(size_t)row * N + col] = v;
        }
    }
}

// ---------------- Causal flash attention ------------------------------------
// grid: (SEQ/128, N_HEADS, BATCH), 128 threads. One thread per query.
// q[64] and acc[64] live in registers; K/V tiles (64x64) in smem, read as
// warp-broadcast (all lanes read the same key row) -> conflict-free.
__global__ void __launch_bounds__(128)
attn_kernel(const float* __restrict__ Q, const float* __restrict__ K,
            const float* __restrict__ V, float* __restrict__ O) {
    __shared__ float Ks[64][64];
    __shared__ float Vs[64][64];

    const int qb = blockIdx.x;
    const int h  = blockIdx.y;
    const int b  = blockIdx.z;
    const int qi = qb * 128 + threadIdx.x;      // query index in [0,SEQ)

    const float* qp = Q + ((size_t)(b * SEQ + qi) * D_MODEL) + h * HEAD_DIM;
    float qreg[64];
    #pragma unroll
    for (int d = 0; d < 64; d++) qreg[d] = qp[d] * 0.125f;  // 1/sqrt(64)

    float m = -1e30f, l = 0.0f;
    float acc[64];
    #pragma unroll
    for (int d = 0; d < 64; d++) acc[d] = 0.0f;

    const int ntiles = 2 * qb + 2;   // keys up to qb*128+127
    for (int t = 0; t < ntiles; t++) {
        const int k0 = t * 64;
        __syncthreads();
        for (int i = threadIdx.x; i < 64 * 16; i += 128) {
            const int r  = i >> 4;
            const int c4 = (i & 15) << 2;
            const size_t goff = ((size_t)(b * SEQ + k0 + r) * D_MODEL) + h * HEAD_DIM + c4;
            *(float4*)&Ks[r][c4] = *(const float4*)(K + goff);
            *(float4*)&Vs[r][c4] = *(const float4*)(V + goff);
        }
        __syncthreads();

        const int jmax = qi - k0 + 1;            // #valid keys in this tile
        if (jmax <= 0) continue;
        const int jlim = jmax < 64 ? jmax : 64;

        for (int c0 = 0; c0 < 64; c0 += 16) {
            if (c0 >= jlim) break;
            float s[16];
            float mloc = m;
            #pragma unroll
            for (int j = 0; j < 16; j++) {
                const int kj = c0 + j;
                const float4* kr = (const float4*)&Ks[kj][0];
                float sum = 0.0f;
                #pragma unroll
                for (int d4 = 0; d4 < 16; d4++) {
                    float4 kk4 = kr[d4];
                    sum += qreg[d4*4+0]*kk4.x + qreg[d4*4+1]*kk4.y
                         + qreg[d4*4+2]*kk4.z + qreg[d4*4+3]*kk4.w;
                }
                s[j] = (kj < jlim) ? sum : -1e30f;
                mloc = fmaxf(mloc, s[j]);
            }
            const float corr = __expf(m - mloc);
            m = mloc;
            l *= corr;
            #pragma unroll
            for (int d = 0; d < 64; d++) acc[d] *= corr;
            #pragma unroll
            for (int j = 0; j < 16; j++) {
                const float p = __expf(s[j] - m);
                l += p;
                const float4* vr = (const float4*)&Vs[c0 + j][0];
                #pragma unroll
                for (int d4 = 0; d4 < 16; d4++) {
                    float4 vv = vr[d4];
                    acc[d4*4+0] = fmaf(p, vv.x, acc[d4*4+0]);
                    acc[d4*4+1] = fmaf(p, vv.y, acc[d4*4+1]);
                    acc[d4*4+2] = fmaf(p, vv.z, acc[d4*4+2]);
                    acc[d4*4+3] = fmaf(p, vv.w, acc[d4*4+3]);
                }
            }
        }
    }

    const float inv = 1.0f / l;
    float* op = O + ((size_t)(b * SEQ + qi) * D_MODEL) + h * HEAD_DIM;
    #pragma unroll
    for (int d = 0; d < 64; d++) op[d] = acc[d] * inv;
}

// ---------------- launch ------------------------------------------------------
extern "C" void kernel_launch(void* const* d_in, const int* in_sizes, int n_in,
                              void* d_out, int out_size) {
    const float* x     = (const float*)d_in[0];
    // d_in[1] = mask (ignored; causality hard-coded)
    const float* wq_w  = (const float*)d_in[2];
    const float* wq_b  = (const float*)d_in[3];
    const float* wk_w  = (const float*)d_in[4];
    const float* wk_b  = (const float*)d_in[5];
    const float* wv_w  = (const float*)d_in[6];
    const float* wv_b  = (const float*)d_in[7];
    const float* wo_w  = (const float*)d_in[8];
    const float* wo_b  = (const float*)d_in[9];
    const float* fc1_w = (const float*)d_in[10];
    const float* fc1_b = (const float*)d_in[11];
    const float* fc2_w = (const float*)d_in[12];
    const float* fc2_b = (const float*)d_in[13];
    const float* ln1_g = (const float*)d_in[14];
    const float* ln1_b = (const float*)d_in[15];
    const float* ln2_g = (const float*)d_in[16];
    const float* ln2_b = (const float*)d_in[17];

    float *h1, *q, *k, *v, *ctx, *x1, *h2, *ff;
    cudaGetSymbolAddress((void**)&h1,  g_h1);
    cudaGetSymbolAddress((void**)&q,   g_q);
    cudaGetSymbolAddress((void**)&k,   g_k);
    cudaGetSymbolAddress((void**)&v,   g_v);
    cudaGetSymbolAddress((void**)&ctx, g_ctx);
    cudaGetSymbolAddress((void**)&x1,  g_x1);
    cudaGetSymbolAddress((void**)&h2,  g_h2);
    cudaGetSymbolAddress((void**)&ff,  g_ff);

    const dim3 gN1024(D_MODEL / 128, M_TOK / 128);  // (8, 32)
    const dim3 gN4096(D_FF    / 128, M_TOK / 128);  // (32, 32)

    // --- attention sub-block (pre-norm) ---
    ln_kernel<<<M_TOK, 256>>>(x, ln1_g, ln1_b, h1);
    gemm_kernel<0><<<gN1024, 256>>>(h1, wq_w, wq_b, nullptr, q, M_TOK, D_MODEL, D_MODEL);
    gemm_kernel<0><<<gN1024, 256>>>(h1, wk_w, wk_b, nullptr, k, M_TOK, D_MODEL, D_MODEL);
    gemm_kernel<0><<<gN1024, 256>>>(h1, wv_w, wv_b, nullptr, v, M_TOK, D_MODEL, D_MODEL);
    attn_kernel<<<dim3(SEQ / 128, N_HEADS, BATCH), 128>>>(q, k, v, ctx);
    gemm_kernel<2><<<gN1024, 256>>>(ctx, wo_w, wo_b, x, x1, M_TOK, D_MODEL, D_MODEL);

    // --- FFN sub-block (pre-norm) ---
    ln_kernel<<<M_TOK, 256>>>(x1, ln2_g, ln2_b, h2);
    gemm_kernel<1><<<gN4096, 256>>>(h2, fc1_w, fc1_b, nullptr, ff, M_TOK, D_FF, D_MODEL);
    gemm_kernel<2><<<gN1024, 256>>>(ff, fc2_w, fc2_b, x1, (float*)d_out, M_TOK, D_MODEL, D_FF);
}

// round 3
// speedup vs baseline: 1.9323x; 1.9323x over previous
#include <cuda_runtime.h>
#include <math.h>
#include <stdint.h>

#define D_MODEL 1024
#define N_HEADS 16
#define HEAD_DIM 64
#define D_FF     4096
#define BATCH    2
#define SEQ      2048
#define M_TOK    (BATCH*SEQ)   /* 4096 token rows */

// ---------------- scratch (static device globals; no allocation) -------------
__device__ float g_h1 [M_TOK*D_MODEL];
__device__ float g_q  [M_TOK*D_MODEL];
__device__ float g_k  [M_TOK*D_MODEL];
__device__ float g_v  [M_TOK*D_MODEL];
__device__ float g_ctx[M_TOK*D_MODEL];
__device__ float g_x1 [M_TOK*D_MODEL];
__device__ float g_h2 [M_TOK*D_MODEL];
__device__ float g_ff [M_TOK*D_FF];
__device__ float g_wr [12*1024*1024];   // tf32-rounded weights

// ---------------- helpers -----------------------------------------------------
__device__ __forceinline__ float tf32r(float x) {
    uint32_t u;
    asm("cvt.rna.tf32.f32 %0, %1;" : "=r"(u) : "f"(x));
    return __uint_as_float(u);
}

// ---------------- LayerNorm (output rounded to tf32) -------------------------
__device__ __forceinline__ float block_reduce_sum(float v, float* sh) {
    #pragma unroll
    for (int o = 16; o > 0; o >>= 1) v += __shfl_down_sync(0xFFFFFFFFu, v, o);
    int lane = threadIdx.x & 31, w = threadIdx.x >> 5;
    if (lane == 0) sh[w] = v;
    __syncthreads();
    if (w == 0) {
        v = (lane < 8) ? sh[lane] : 0.0f;
        #pragma unroll
        for (int o = 4; o > 0; o >>= 1) v += __shfl_down_sync(0xFFFFFFFFu, v, o);
        if (lane == 0) sh[0] = v;
    }
    __syncthreads();
    float r = sh[0];
    __syncthreads();
    return r;
}

__global__ void ln_kernel(const float* __restrict__ x,
                          const float* __restrict__ gamma,
                          const float* __restrict__ beta,
                          float* __restrict__ out) {
    __shared__ float sh[32];
    const int row = blockIdx.x;
    const float* xr = x + (size_t)row * D_MODEL;
    float v[4];
    float s = 0.0f;
    #pragma unroll
    for (int i = 0; i < 4; i++) { v[i] = xr[threadIdx.x + i * 256]; s += v[i]; }
    float mean = block_reduce_sum(s, sh) * (1.0f / D_MODEL);
    float s2 = 0.0f;
    #pragma unroll
    for (int i = 0; i < 4; i++) { float d = v[i] - mean; s2 += d * d; }
    float var = block_reduce_sum(s2, sh) * (1.0f / D_MODEL);
    float rstd = rsqrtf(var + 1e-5f);
    float* orow = out + (size_t)row * D_MODEL;
    #pragma unroll
    for (int i = 0; i < 4; i++) {
        int idx = threadIdx.x + i * 256;
        orow[idx] = tf32r((v[i] - mean) * rstd * gamma[idx] + beta[idx]);
    }
}

// ---------------- weight rounding pass ---------------------------------------
__global__ void round_tf32_kernel(const float* __restrict__ in, float* __restrict__ out, int n4) {
    int i = blockIdx.x * blockDim.x + threadIdx.x;
    if (i < n4) {
        float4 v = ((const float4*)in)[i];
        v.x = tf32r(v.x); v.y = tf32r(v.y); v.z = tf32r(v.z); v.w = tf32r(v.w);
        ((float4*)out)[i] = v;
    }
}

// ---------------- TF32 mma.sync GEMM:  C[M,N] = A[M,K] @ W[N,K]^T ------------
// 128x128 tile, BK=32, 256 threads (8 warps, each 64x32 via m16n8k8 tiles),
// 2-stage cp.async double buffer, fp32 register accumulators.
// Smem per stage: A[128][36] + W[128][36] floats (pad 4 -> conflict-free frags).
// EPI: 0 = +bias; 1 = +bias, GELU, round tf32; 2 = +bias + residual.
#define STG_FLOATS   (128*36)           /* per matrix per stage */
#define STAGE_FLOATS (2*STG_FLOATS)     /* A + W */
#define GEMM_SMEM_BYTES (2*STAGE_FLOATS*4 + 512)

__device__ __forceinline__ void mma_tf32(float* d, const uint32_t* a, const uint32_t* b) {
    asm volatile(
        "mma.sync.aligned.m16n8k8.row.col.f32.tf32.tf32.f32 "
        "{%0,%1,%2,%3}, {%4,%5,%6,%7}, {%8,%9}, {%0,%1,%2,%3};"
        : "+f"(d[0]), "+f"(d[1]), "+f"(d[2]), "+f"(d[3])
        : "r"(a[0]), "r"(a[1]), "r"(a[2]), "r"(a[3]), "r"(b[0]), "r"(b[1]));
}

__device__ __forceinline__ void load_chunk(
    float* smem_f, const float* __restrict__ A, const float* __restrict__ W,
    int bm, int bn, int K, int c, int s, int tid) {
    float* stage = smem_f + s * STAGE_FLOATS;
    #pragma unroll
    for (int it = 0; it < 8; it++) {
        int i = tid + it * 256;          // 0..2047
        bool isA = i < 1024;
        int j = i & 1023;
        int row = j >> 3, c16 = j & 7;   // row 0..127, k-quad 0..7
        float* dst = stage + (isA ? 0 : STG_FLOATS) + row * 36 + c16 * 4;
        const float* src = (isA ? A + (size_t)(bm + row) * K
                                : W + (size_t)(bn + row) * K) + c * 32 + c16 * 4;
        uint32_t dsm;
        asm("{ .reg .u64 t; cvta.to.shared.u64 t, %1; cvt.u32.u64 %0, t; }" : "=r"(dsm) : "l"(dst));
        asm volatile("cp.async.cg.shared.global [%0], [%1], 16;" :: "r"(dsm), "l"(src));
    }
    asm volatile("cp.async.commit_group;" ::: "memory");
}

template<int EPI>
__global__ void __launch_bounds__(256, 2)
mma_gemm(const float* __restrict__ A, const float* __restrict__ W,
         const float* __restrict__ bias, const float* __restrict__ res,
         float* __restrict__ C, int M, int N, int K) {
    extern __shared__ char smem[];
    float* smem_f = (float*)smem;
    float* sbias  = smem_f + 2 * STAGE_FLOATS;

    const int tid  = threadIdx.x;
    const int wid  = tid >> 5, lane = tid & 31;
    const int wm   = wid >> 2, wn = wid & 3;         // 2 x 4 warp grid
    const int bm   = blockIdx.y * 128, bn = blockIdx.x * 128;
    const int NC   = K >> 5;

    if (tid < 128) sbias[tid] = bias[bn + tid];

    float acc[4][4][4];
    #pragma unroll
    for (int mt = 0; mt < 4; mt++)
        #pragma unroll
        for (int nt = 0; nt < 4; nt++)
            #pragma unroll
            for (int e = 0; e < 4; e++) acc[mt][nt][e] = 0.0f;

    load_chunk(smem_f, A, W, bm, bn, K, 0, 0, tid);

    const int lr4 = lane >> 2;     // 0..7
    const int lc  = lane & 3;      // 0..3

    for (int c = 0; c < NC; c++) {
        __syncthreads();           // all warps done reading stage (c+1)&1 (iter c-1)
        if (c + 1 < NC) {
            load_chunk(smem_f, A, W, bm, bn, K, c + 1, (c + 1) & 1, tid);
            asm volatile("cp.async.wait_group 1;" ::: "memory");
        } else {
            asm volatile("cp.async.wait_group 0;" ::: "memory");
        }
        __syncthreads();           // stage c&1 visible to all

        const float* As = smem_f + (c & 1) * STAGE_FLOATS;
        const float* Ws = As + STG_FLOATS;

        #pragma unroll
        for (int ks = 0; ks < 4; ks++) {
            const int k0 = ks * 8 + lc;
            uint32_t a[4][4], b[4][2];
            #pragma unroll
            for (int mt = 0; mt < 4; mt++) {
                const int r = wm * 64 + mt * 16 + lr4;
                a[mt][0] = __float_as_uint(As[r * 36 + k0]);
                a[mt][1] = __float_as_uint(As[(r + 8) * 36 + k0]);
                a[mt][2] = __float_as_uint(As[r * 36 + k0 + 4]);
                a[mt][3] = __float_as_uint(As[(r + 8) * 36 + k0 + 4]);
            }
            #pragma unroll
            for (int nt = 0; nt < 4; nt++) {
                const int nr = wn * 32 + nt * 8 + lr4;
                b[nt][0] = __float_as_uint(Ws[nr * 36 + k0]);
                b[nt][1] = __float_as_uint(Ws[nr * 36 + k0 + 4]);
            }
            #pragma unroll
            for (int mt = 0; mt < 4; mt++)
                #pragma unroll
                for (int nt = 0; nt < 4; nt++)
                    mma_tf32(acc[mt][nt], a[mt], b[nt]);
        }
    }

    // ---- epilogue ----
    #pragma unroll
    for (int mt = 0; mt < 4; mt++) {
        const int row0 = bm + wm * 64 + mt * 16 + lr4;
        #pragma unroll
        for (int nt = 0; nt < 4; nt++) {
            const int coll = wn * 32 + nt * 8 + lc * 2;   // local col within tile
            const int col  = bn + coll;
            #pragma unroll
            for (int half = 0; half < 2; half++) {
                const int row = row0 + half * 8;
                float2 o;
                o.x = acc[mt][nt][half * 2 + 0] + sbias[coll];
                o.y = acc[mt][nt][half * 2 + 1] + sbias[coll + 1];
                if (EPI == 1) {
                    o.x = tf32r(0.5f * o.x * (1.0f + erff(o.x * 0.70710678118654752f)));
                    o.y = tf32r(0.5f * o.y * (1.0f + erff(o.y * 0.70710678118654752f)));
                } else if (EPI == 2) {
                    const float2 rv = *(const float2*)(res + (size_t)row * N + col);
                    o.x += rv.x; o.y += rv.y;
                }
                *(float2*)(C + (size_t)row * N + col) = o;
            }
        }
    }
}

// ---------------- Causal flash attention (fp32, output rounded) --------------
__global__ void __launch_bounds__(128)
attn_kernel(const float* __restrict__ Q, const float* __restrict__ K,
            const float* __restrict__ V, float* __restrict__ O) {
    __shared__ float Ks[64][64];
    __shared__ float Vs[64][64];

    const int qb = blockIdx.x;
    const int h  = blockIdx.y;
    const int b  = blockIdx.z;
    const int qi = qb * 128 + threadIdx.x;

    const float* qp = Q + ((size_t)(b * SEQ + qi) * D_MODEL) + h * HEAD_DIM;
    float qreg[64];
    #pragma unroll
    for (int d = 0; d < 64; d++) qreg[d] = qp[d] * 0.125f;

    float m = -1e30f, l = 0.0f;
    float acc[64];
    #pragma unroll
    for (int d = 0; d < 64; d++) acc[d] = 0.0f;

    const int ntiles = 2 * qb + 2;
    for (int t = 0; t < ntiles; t++) {
        const int k0 = t * 64;
        __syncthreads();
        for (int i = threadIdx.x; i < 64 * 16; i += 128) {
            const int r  = i >> 4;
            const int c4 = (i & 15) << 2;
            const size_t goff = ((size_t)(b * SEQ + k0 + r) * D_MODEL) + h * HEAD_DIM + c4;
            *(float4*)&Ks[r][c4] = *(const float4*)(K + goff);
            *(float4*)&Vs[r][c4] = *(const float4*)(V + goff);
        }
        __syncthreads();

        const int jmax = qi - k0 + 1;
        if (jmax <= 0) continue;
        const int jlim = jmax < 64 ? jmax : 64;

        for (int c0 = 0; c0 < 64; c0 += 16) {
            if (c0 >= jlim) break;
            float s[16];
            float mloc = m;
            #pragma unroll
            for (int j = 0; j < 16; j++) {
                const int kj = c0 + j;
                const float4* kr = (const float4*)&Ks[kj][0];
                float sum = 0.0f;
                #pragma unroll
                for (int d4 = 0; d4 < 16; d4++) {
                    float4 kk4 = kr[d4];
                    sum += qreg[d4*4+0]*kk4.x + qreg[d4*4+1]*kk4.y
                         + qreg[d4*4+2]*kk4.z + qreg[d4*4+3]*kk4.w;
                }
                s[j] = (kj < jlim) ? sum : -1e30f;
                mloc = fmaxf(mloc, s[j]);
            }
            const float corr = __expf(m - mloc);
            m = mloc;
            l *= corr;
            #pragma unroll
            for (int d = 0; d < 64; d++) acc[d] *= corr;
            #pragma unroll
            for (int j = 0; j < 16; j++) {
                const float p = __expf(s[j] - m);
                l += p;
                const float4* vr = (const float4*)&Vs[c0 + j][0];
                #pragma unroll
                for (int d4 = 0; d4 < 16; d4++) {
                    float4 vv = vr[d4];
                    acc[d4*4+0] = fmaf(p, vv.x, acc[d4*4+0]);
                    acc[d4*4+1] = fmaf(p, vv.y, acc[d4*4+1]);
                    acc[d4*4+2] = fmaf(p, vv.z, acc[d4*4+2]);
                    acc[d4*4+3] = fmaf(p, vv.w, acc[d4*4+3]);
                }
            }
        }
    }

    const float inv = 1.0f / l;
    float* op = O + ((size_t)(b * SEQ + qi) * D_MODEL) + h * HEAD_DIM;
    #pragma unroll
    for (int d = 0; d < 64; d++) op[d] = tf32r(acc[d] * inv);  // ctx feeds Wo GEMM
}

// ---------------- launch ------------------------------------------------------
extern "C" void kernel_launch(void* const* d_in, const int* in_sizes, int n_in,
                              void* d_out, int out_size) {
    const float* x     = (const float*)d_in[0];
    const float* wq_w  = (const float*)d_in[2];
    const float* wq_b  = (const float*)d_in[3];
    const float* wk_w  = (const float*)d_in[4];
    const float* wk_b  = (const float*)d_in[5];
    const float* wv_w  = (const float*)d_in[6];
    const float* wv_b  = (const float*)d_in[7];
    const float* wo_w  = (const float*)d_in[8];
    const float* wo_b  = (const float*)d_in[9];
    const float* fc1_w = (const float*)d_in[10];
    const float* fc1_b = (const float*)d_in[11];
    const float* fc2_w = (const float*)d_in[12];
    const float* fc2_b = (const float*)d_in[13];
    const float* ln1_g = (const float*)d_in[14];
    const float* ln1_b = (const float*)d_in[15];
    const float* ln2_g = (const float*)d_in[16];
    const float* ln2_b = (const float*)d_in[17];

    float *h1, *q, *k, *v, *ctx, *x1, *h2, *ff, *wr;
    cudaGetSymbolAddress((void**)&h1,  g_h1);
    cudaGetSymbolAddress((void**)&q,   g_q);
    cudaGetSymbolAddress((void**)&k,   g_k);
    cudaGetSymbolAddress((void**)&v,   g_v);
    cudaGetSymbolAddress((void**)&ctx, g_ctx);
    cudaGetSymbolAddress((void**)&x1,  g_x1);
    cudaGetSymbolAddress((void**)&h2,  g_h2);
    cudaGetSymbolAddress((void**)&ff,  g_ff);
    cudaGetSymbolAddress((void**)&wr,  g_wr);

    cudaFuncSetAttribute(mma_gemm<0>, cudaFuncAttributeMaxDynamicSharedMemorySize, GEMM_SMEM_BYTES);
    cudaFuncSetAttribute(mma_gemm<1>, cudaFuncAttributeMaxDynamicSharedMemorySize, GEMM_SMEM_BYTES);
    cudaFuncSetAttribute(mma_gemm<2>, cudaFuncAttributeMaxDynamicSharedMemorySize, GEMM_SMEM_BYTES);

    const int MM = 1024 * 1024;
    float* wr_q   = wr + 0 * MM;
    float* wr_k   = wr + 1 * MM;
    float* wr_v   = wr + 2 * MM;
    float* wr_o   = wr + 3 * MM;
    float* wr_fc1 = wr + 4 * MM;
    float* wr_fc2 = wr + 8 * MM;

    round_tf32_kernel<<<(1*MM/4 + 255)/256, 256>>>(wq_w,  wr_q,   1*MM/4);
    round_tf32_kernel<<<(1*MM/4 + 255)/256, 256>>>(wk_w,  wr_k,   1*MM/4);
    round_tf32_kernel<<<(1*MM/4 + 255)/256, 256>>>(wv_w,  wr_v,   1*MM/4);
    round_tf32_kernel<<<(1*MM/4 + 255)/256, 256>>>(wo_w,  wr_o,   1*MM/4);
    round_tf32_kernel<<<(4*MM/4 + 255)/256, 256>>>(fc1_w, wr_fc1, 4*MM/4);
    round_tf32_kernel<<<(4*MM/4 + 255)/256, 256>>>(fc2_w, wr_fc2, 4*MM/4);

    const dim3 gN1024(D_MODEL / 128, M_TOK / 128);  // (8, 32)
    const dim3 gN4096(D_FF    / 128, M_TOK / 128);  // (32, 32)

    // --- attention sub-block (pre-norm) ---
    ln_kernel<<<M_TOK, 256>>>(x, ln1_g, ln1_b, h1);
    mma_gemm<0><<<gN1024, 256, GEMM_SMEM_BYTES>>>(h1, wr_q, wq_b, nullptr, q, M_TOK, D_MODEL, D_MODEL);
    mma_gemm<0><<<gN1024, 256, GEMM_SMEM_BYTES>>>(h1, wr_k, wk_b, nullptr, k, M_TOK, D_MODEL, D_MODEL);
    mma_gemm<0><<<gN1024, 256, GEMM_SMEM_BYTES>>>(h1, wr_v, wv_b, nullptr, v, M_TOK, D_MODEL, D_MODEL);
    attn_kernel<<<dim3(SEQ / 128, N_HEADS, BATCH), 128>>>(q, k, v, ctx);
    mma_gemm<2><<<gN1024, 256, GEMM_SMEM_BYTES>>>(ctx, wr_o, wo_b, x, x1, M_TOK, D_MODEL, D_MODEL);

    // --- FFN sub-block (pre-norm) ---
    ln_kernel<<<M_TOK, 256>>>(x1, ln2_g, ln2_b, h2);
    mma_gemm<1><<<gN4096, 256, GEMM_SMEM_BYTES>>>(h2, wr_fc1, fc1_b, nullptr, ff, M_TOK, D_FF, D_MODEL);
    mma_gemm<2><<<gN1024, 256, GEMM_SMEM_BYTES>>>(ff, wr_fc2, fc2_b, x1, (float*)d_out, M_TOK, D_MODEL, D_FF);
}

// round 4
// speedup vs baseline: 4.0516x; 2.0968x over previous
#include <cuda_runtime.h>
#include <math.h>
#include <stdint.h>

#define D_MODEL 1024
#define N_HEADS 16
#define HEAD_DIM 64
#define D_FF     4096
#define BATCH    2
#define SEQ      2048
#define M_TOK    (BATCH*SEQ)   /* 4096 token rows */

// ---------------- scratch (static device globals; no allocation) -------------
__device__ float g_h1 [M_TOK*D_MODEL];
__device__ float g_q  [M_TOK*D_MODEL];
__device__ float g_k  [M_TOK*D_MODEL];
__device__ float g_v  [M_TOK*D_MODEL];
__device__ float g_ctx[M_TOK*D_MODEL];
__device__ float g_x1 [M_TOK*D_MODEL];
__device__ float g_h2 [M_TOK*D_MODEL];
__device__ float g_ff [M_TOK*D_FF];
__device__ float g_wr [12*1024*1024];   // tf32-rounded weights

// ---------------- helpers -----------------------------------------------------
__device__ __forceinline__ float tf32r(float x) {
    uint32_t u;
    asm("cvt.rna.tf32.f32 %0, %1;" : "=r"(u) : "f"(x));
    return __uint_as_float(u);
}
__device__ __forceinline__ void mma_tf32(float* d, const uint32_t* a, const uint32_t* b) {
    asm volatile(
        "mma.sync.aligned.m16n8k8.row.col.f32.tf32.tf32.f32 "
        "{%0,%1,%2,%3}, {%4,%5,%6,%7}, {%8,%9}, {%0,%1,%2,%3};"
        : "+f"(d[0]), "+f"(d[1]), "+f"(d[2]), "+f"(d[3])
        : "r"(a[0]), "r"(a[1]), "r"(a[2]), "r"(a[3]), "r"(b[0]), "r"(b[1]));
}

// ---------------- LayerNorm (output rounded to tf32) -------------------------
__device__ __forceinline__ float block_reduce_sum(float v, float* sh) {
    #pragma unroll
    for (int o = 16; o > 0; o >>= 1) v += __shfl_down_sync(0xFFFFFFFFu, v, o);
    int lane = threadIdx.x & 31, w = threadIdx.x >> 5;
    if (lane == 0) sh[w] = v;
    __syncthreads();
    if (w == 0) {
        v = (lane < 8) ? sh[lane] : 0.0f;
        #pragma unroll
        for (int o = 4; o > 0; o >>= 1) v += __shfl_down_sync(0xFFFFFFFFu, v, o);
        if (lane == 0) sh[0] = v;
    }
    __syncthreads();
    float r = sh[0];
    __syncthreads();
    return r;
}

__global__ void ln_kernel(const float* __restrict__ x,
                          const float* __restrict__ gamma,
                          const float* __restrict__ beta,
                          float* __restrict__ out) {
    __shared__ float sh[32];
    const int row = blockIdx.x;
    const float* xr = x + (size_t)row * D_MODEL;
    float v[4];
    float s = 0.0f;
    #pragma unroll
    for (int i = 0; i < 4; i++) { v[i] = xr[threadIdx.x + i * 256]; s += v[i]; }
    float mean = block_reduce_sum(s, sh) * (1.0f / D_MODEL);
    float s2 = 0.0f;
    #pragma unroll
    for (int i = 0; i < 4; i++) { float d = v[i] - mean; s2 += d * d; }
    float var = block_reduce_sum(s2, sh) * (1.0f / D_MODEL);
    float rstd = rsqrtf(var + 1e-5f);
    float* orow = out + (size_t)row * D_MODEL;
    #pragma unroll
    for (int i = 0; i < 4; i++) {
        int idx = threadIdx.x + i * 256;
        orow[idx] = tf32r((v[i] - mean) * rstd * gamma[idx] + beta[idx]);
    }
}

// ---------------- weight rounding pass ---------------------------------------
__global__ void round_tf32_kernel(const float* __restrict__ in, float* __restrict__ out, int n4) {
    int i = blockIdx.x * blockDim.x + threadIdx.x;
    if (i < n4) {
        float4 v = ((const float4*)in)[i];
        v.x = tf32r(v.x); v.y = tf32r(v.y); v.z = tf32r(v.z); v.w = tf32r(v.w);
        ((float4*)out)[i] = v;
    }
}

// ---------------- TF32 mma.sync GEMM:  C[M,N] = A[M,K] @ W[N,K]^T ------------
#define STG_FLOATS   (128*36)
#define STAGE_FLOATS (2*STG_FLOATS)
#define GEMM_SMEM_BYTES (2*STAGE_FLOATS*4 + 512)

__device__ __forceinline__ void load_chunk(
    float* smem_f, const float* __restrict__ A, const float* __restrict__ W,
    int bm, int bn, int K, int c, int s, int tid) {
    float* stage = smem_f + s * STAGE_FLOATS;
    #pragma unroll
    for (int it = 0; it < 8; it++) {
        int i = tid + it * 256;
        bool isA = i < 1024;
        int j = i & 1023;
        int row = j >> 3, c16 = j & 7;
        float* dst = stage + (isA ? 0 : STG_FLOATS) + row * 36 + c16 * 4;
        const float* src = (isA ? A + (size_t)(bm + row) * K
                                : W + (size_t)(bn + row) * K) + c * 32 + c16 * 4;
        uint32_t dsm;
        asm("{ .reg .u64 t; cvta.to.shared.u64 t, %1; cvt.u32.u64 %0, t; }" : "=r"(dsm) : "l"(dst));
        asm volatile("cp.async.cg.shared.global [%0], [%1], 16;" :: "r"(dsm), "l"(src));
    }
    asm volatile("cp.async.commit_group;" ::: "memory");
}

template<int EPI>
__global__ void __launch_bounds__(256, 2)
mma_gemm(const float* __restrict__ A, const float* __restrict__ W,
         const float* __restrict__ bias, const float* __restrict__ res,
         float* __restrict__ C, int M, int N, int K) {
    extern __shared__ char smem[];
    float* smem_f = (float*)smem;
    float* sbias  = smem_f + 2 * STAGE_FLOATS;

    const int tid  = threadIdx.x;
    const int wid  = tid >> 5, lane = tid & 31;
    const int wm   = wid >> 2, wn = wid & 3;
    const int bm   = blockIdx.y * 128, bn = blockIdx.x * 128;
    const int NC   = K >> 5;

    if (tid < 128) sbias[tid] = bias[bn + tid];

    float acc[4][4][4];
    #pragma unroll
    for (int mt = 0; mt < 4; mt++)
        #pragma unroll
        for (int nt = 0; nt < 4; nt++)
            #pragma unroll
            for (int e = 0; e < 4; e++) acc[mt][nt][e] = 0.0f;

    load_chunk(smem_f, A, W, bm, bn, K, 0, 0, tid);

    const int lr4 = lane >> 2;
    const int lc  = lane & 3;

    for (int c = 0; c < NC; c++) {
        __syncthreads();
        if (c + 1 < NC) {
            load_chunk(smem_f, A, W, bm, bn, K, c + 1, (c + 1) & 1, tid);
            asm volatile("cp.async.wait_group 1;" ::: "memory");
        } else {
            asm volatile("cp.async.wait_group 0;" ::: "memory");
        }
        __syncthreads();

        const float* As = smem_f + (c & 1) * STAGE_FLOATS;
        const float* Ws = As + STG_FLOATS;

        #pragma unroll
        for (int ks = 0; ks < 4; ks++) {
            const int k0 = ks * 8 + lc;
            uint32_t a[4][4], b[4][2];
            #pragma unroll
            for (int mt = 0; mt < 4; mt++) {
                const int r = wm * 64 + mt * 16 + lr4;
                a[mt][0] = __float_as_uint(As[r * 36 + k0]);
                a[mt][1] = __float_as_uint(As[(r + 8) * 36 + k0]);
                a[mt][2] = __float_as_uint(As[r * 36 + k0 + 4]);
                a[mt][3] = __float_as_uint(As[(r + 8) * 36 + k0 + 4]);
            }
            #pragma unroll
            for (int nt = 0; nt < 4; nt++) {
                const int nr = wn * 32 + nt * 8 + lr4;
                b[nt][0] = __float_as_uint(Ws[nr * 36 + k0]);
                b[nt][1] = __float_as_uint(Ws[nr * 36 + k0 + 4]);
            }
            #pragma unroll
            for (int mt = 0; mt < 4; mt++)
                #pragma unroll
                for (int nt = 0; nt < 4; nt++)
                    mma_tf32(acc[mt][nt], a[mt], b[nt]);
        }
    }

    #pragma unroll
    for (int mt = 0; mt < 4; mt++) {
        const int row0 = bm + wm * 64 + mt * 16 + lr4;
        #pragma unroll
        for (int nt = 0; nt < 4; nt++) {
            const int coll = wn * 32 + nt * 8 + lc * 2;
            const int col  = bn + coll;
            #pragma unroll
            for (int half = 0; half < 2; half++) {
                const int row = row0 + half * 8;
                float2 o;
                o.x = acc[mt][nt][half * 2 + 0] + sbias[coll];
                o.y = acc[mt][nt][half * 2 + 1] + sbias[coll + 1];
                if (EPI == 1) {
                    o.x = tf32r(0.5f * o.x * (1.0f + erff(o.x * 0.70710678118654752f)));
                    o.y = tf32r(0.5f * o.y * (1.0f + erff(o.y * 0.70710678118654752f)));
                } else if (EPI == 2) {
                    const float2 rv = *(const float2*)(res + (size_t)row * N + col);
                    o.x += rv.x; o.y += rv.y;
                }
                *(float2*)(C + (size_t)row * N + col) = o;
            }
        }
    }
}

// ---------------- Tensor-core causal flash attention (tf32 mma) ---------------
// CTA: 128 queries x 1 head. 4 warps, each 32 q-rows (2 m-tiles of 16).
// Key tiles of 64. Smem: Q[128][68], K[64][68], Vt[64][68], P per-warp [32][68].
#define AT_STRIDE 68
#define AT_SMEM ((128*AT_STRIDE + 64*AT_STRIDE + 64*AT_STRIDE + 4*32*AT_STRIDE)*4)

__global__ void __launch_bounds__(128)
attn_tc(const float* __restrict__ Q, const float* __restrict__ K,
        const float* __restrict__ V, float* __restrict__ O) {
    extern __shared__ float sm[];
    float* Qs  = sm;                                   // [128][68]
    float* Ks  = Qs + 128 * AT_STRIDE;                 // [64][68]
    float* Vts = Ks + 64 * AT_STRIDE;                  // [64][68] (d-major)
    const int tid = threadIdx.x;
    const int wid = tid >> 5, lane = tid & 31;
    const int lr4 = lane >> 2, lc = lane & 3;
    float* Ps = Vts + 64 * AT_STRIDE + wid * 32 * AT_STRIDE;  // per-warp [32][68]

    const int qb = blockIdx.x, h = blockIdx.y, b = blockIdx.z;
    const size_t qbase = ((size_t)(b * SEQ + qb * 128) * D_MODEL) + h * HEAD_DIM;

    // load Q tile (scaled by 1/sqrt(dh), tf32-rounded)
    #pragma unroll
    for (int it = 0; it < 16; it++) {
        const int i = tid + it * 128;
        const int row = i >> 4, c4 = (i & 15) * 4;
        float4 v4 = *(const float4*)(Q + qbase + (size_t)row * D_MODEL + c4);
        float* d = Qs + row * AT_STRIDE + c4;
        d[0] = tf32r(v4.x * 0.125f); d[1] = tf32r(v4.y * 0.125f);
        d[2] = tf32r(v4.z * 0.125f); d[3] = tf32r(v4.w * 0.125f);
    }

    float m[4], l[4], acc[2][8][4];
    #pragma unroll
    for (int s = 0; s < 4; s++) { m[s] = -1e30f; l[s] = 0.0f; }
    #pragma unroll
    for (int mt = 0; mt < 2; mt++)
        #pragma unroll
        for (int nt = 0; nt < 8; nt++)
            #pragma unroll
            for (int e = 0; e < 4; e++) acc[mt][nt][e] = 0.0f;

    const int ntk = 2 * qb + 2;
    for (int kt = 0; kt < ntk; kt++) {
        __syncthreads();   // prior-iter reads done (covers Q store on iter 0)
        const size_t kbase = ((size_t)(b * SEQ + kt * 64) * D_MODEL) + h * HEAD_DIM;
        // K tile (row-major)
        #pragma unroll
        for (int it = 0; it < 8; it++) {
            const int i = tid + it * 128;
            const int row = i >> 4, c4 = (i & 15) * 4;
            float4 v4 = *(const float4*)(K + kbase + (size_t)row * D_MODEL + c4);
            float* d = Ks + row * AT_STRIDE + c4;
            d[0] = tf32r(v4.x); d[1] = tf32r(v4.y); d[2] = tf32r(v4.z); d[3] = tf32r(v4.w);
        }
        // V tile transposed -> Vt[d][tok]
        {
            const int tok = tid >> 1, dbase = (tid & 1) * 32;
            const float* vp = V + kbase + (size_t)tok * D_MODEL + dbase;
            #pragma unroll
            for (int j = 0; j < 8; j++) {
                float4 v4 = *(const float4*)(vp + j * 4);
                const int d0 = dbase + j * 4;
                Vts[(d0 + 0) * AT_STRIDE + tok] = tf32r(v4.x);
                Vts[(d0 + 1) * AT_STRIDE + tok] = tf32r(v4.y);
                Vts[(d0 + 2) * AT_STRIDE + tok] = tf32r(v4.z);
                Vts[(d0 + 3) * AT_STRIDE + tok] = tf32r(v4.w);
            }
        }
        __syncthreads();

        // ---- S = Q @ K^T ----
        float s[2][8][4];
        #pragma unroll
        for (int mt = 0; mt < 2; mt++)
            #pragma unroll
            for (int nt = 0; nt < 8; nt++)
                #pragma unroll
                for (int e = 0; e < 4; e++) s[mt][nt][e] = 0.0f;

        #pragma unroll
        for (int ks = 0; ks < 8; ks++) {
            const int k0 = ks * 8 + lc;
            uint32_t a[2][4];
            #pragma unroll
            for (int mt = 0; mt < 2; mt++) {
                const int r = wid * 32 + mt * 16 + lr4;
                a[mt][0] = __float_as_uint(Qs[r * AT_STRIDE + k0]);
                a[mt][1] = __float_as_uint(Qs[(r + 8) * AT_STRIDE + k0]);
                a[mt][2] = __float_as_uint(Qs[r * AT_STRIDE + k0 + 4]);
                a[mt][3] = __float_as_uint(Qs[(r + 8) * AT_STRIDE + k0 + 4]);
            }
            #pragma unroll
            for (int nt = 0; nt < 8; nt++) {
                uint32_t bb[2];
                const int nr = nt * 8 + lr4;
                bb[0] = __float_as_uint(Ks[nr * AT_STRIDE + k0]);
                bb[1] = __float_as_uint(Ks[nr * AT_STRIDE + k0 + 4]);
                mma_tf32(s[0][nt], a[0], bb);
                mma_tf32(s[1][nt], a[1], bb);
            }
        }

        // causal mask (only diagonal-region tiles)
        if (kt >= 2 * qb) {
            const int rbase = qb * 128 + wid * 32;
            #pragma unroll
            for (int mt = 0; mt < 2; mt++) {
                const int row0 = rbase + mt * 16 + lr4;
                #pragma unroll
                for (int nt = 0; nt < 8; nt++) {
                    const int col0 = kt * 64 + nt * 8 + 2 * lc;
                    if (col0     > row0)     s[mt][nt][0] = -1e9f;
                    if (col0 + 1 > row0)     s[mt][nt][1] = -1e9f;
                    if (col0     > row0 + 8) s[mt][nt][2] = -1e9f;
                    if (col0 + 1 > row0 + 8) s[mt][nt][3] = -1e9f;
                }
            }
        }

        // ---- online softmax ----
        #pragma unroll
        for (int mt = 0; mt < 2; mt++)
            #pragma unroll
            for (int hf = 0; hf < 2; hf++) {
                const int slot = mt * 2 + hf;
                float mx = m[slot];
                #pragma unroll
                for (int nt = 0; nt < 8; nt++)
                    mx = fmaxf(mx, fmaxf(s[mt][nt][hf * 2], s[mt][nt][hf * 2 + 1]));
                mx = fmaxf(mx, __shfl_xor_sync(0xFFFFFFFFu, mx, 1));
                mx = fmaxf(mx, __shfl_xor_sync(0xFFFFFFFFu, mx, 2));
                const float corr = __expf(m[slot] - mx);
                m[slot] = mx;
                float sum = 0.0f;
                #pragma unroll
                for (int nt = 0; nt < 8; nt++) {
                    float p0 = __expf(s[mt][nt][hf * 2]     - mx);
                    float p1 = __expf(s[mt][nt][hf * 2 + 1] - mx);
                    s[mt][nt][hf * 2] = p0; s[mt][nt][hf * 2 + 1] = p1;
                    sum += p0 + p1;
                }
                sum += __shfl_xor_sync(0xFFFFFFFFu, sum, 1);
                sum += __shfl_xor_sync(0xFFFFFFFFu, sum, 2);
                l[slot] = l[slot] * corr + sum;
                #pragma unroll
                for (int nt = 0; nt < 8; nt++) {
                    acc[mt][nt][hf * 2]     *= corr;
                    acc[mt][nt][hf * 2 + 1] *= corr;
                }
            }

        // ---- stage P to per-warp smem (tf32-rounded) ----
        #pragma unroll
        for (int mt = 0; mt < 2; mt++)
            #pragma unroll
            for (int nt = 0; nt < 8; nt++) {
                float* p0 = Ps + (mt * 16 + lr4) * AT_STRIDE + nt * 8 + 2 * lc;
                float* p1 = Ps + (mt * 16 + lr4 + 8) * AT_STRIDE + nt * 8 + 2 * lc;
                p0[0] = tf32r(s[mt][nt][0]); p0[1] = tf32r(s[mt][nt][1]);
                p1[0] = tf32r(s[mt][nt][2]); p1[1] = tf32r(s[mt][nt][3]);
            }
        __syncwarp();

        // ---- O += P @ V ----
        #pragma unroll
        for (int ks = 0; ks < 8; ks++) {
            const int k0 = ks * 8 + lc;
            uint32_t a[2][4];
            #pragma unroll
            for (int mt = 0; mt < 2; mt++) {
                const int r = mt * 16 + lr4;
                a[mt][0] = __float_as_uint(Ps[r * AT_STRIDE + k0]);
                a[mt][1] = __float_as_uint(Ps[(r + 8) * AT_STRIDE + k0]);
                a[mt][2] = __float_as_uint(Ps[r * AT_STRIDE + k0 + 4]);
                a[mt][3] = __float_as_uint(Ps[(r + 8) * AT_STRIDE + k0 + 4]);
            }
            #pragma unroll
            for (int nt = 0; nt < 8; nt++) {
                uint32_t bb[2];
                const int nr = nt * 8 + lr4;
                bb[0] = __float_as_uint(Vts[nr * AT_STRIDE + k0]);
                bb[1] = __float_as_uint(Vts[nr * AT_STRIDE + k0 + 4]);
                mma_tf32(acc[0][nt], a[0], bb);
                mma_tf32(acc[1][nt], a[1], bb);
            }
        }
        __syncwarp();
    }

    // ---- epilogue: O = acc / l (tf32-rounded; feeds Wo GEMM) ----
    float inv[4];
    #pragma unroll
    for (int s = 0; s < 4; s++) inv[s] = 1.0f / l[s];
    #pragma unroll
    for (int mt = 0; mt < 2; mt++) {
        const int row0 = qb * 128 + wid * 32 + mt * 16 + lr4;
        #pragma unroll
        for (int nt = 0; nt < 8; nt++) {
            const int col = h * HEAD_DIM + nt * 8 + 2 * lc;
            float2 o0, o1;
            o0.x = tf32r(acc[mt][nt][0] * inv[mt * 2]);
            o0.y = tf32r(acc[mt][nt][1] * inv[mt * 2]);
            o1.x = tf32r(acc[mt][nt][2] * inv[mt * 2 + 1]);
            o1.y = tf32r(acc[mt][nt][3] * inv[mt * 2 + 1]);
            *(float2*)(O + (size_t)(b * SEQ + row0) * D_MODEL + col) = o0;
            *(float2*)(O + (size_t)(b * SEQ + row0 + 8) * D_MODEL + col) = o1;
        }
    }
}

// ---------------- launch ------------------------------------------------------
extern "C" void kernel_launch(void* const* d_in, const int* in_sizes, int n_in,
                              void* d_out, int out_size) {
    const float* x     = (const float*)d_in[0];
    const float* wq_w  = (const float*)d_in[2];
    const float* wq_b  = (const float*)d_in[3];
    const float* wk_w  = (const float*)d_in[4];
    const float* wk_b  = (const float*)d_in[5];
    const float* wv_w  = (const float*)d_in[6];
    const float* wv_b  = (const float*)d_in[7];
    const float* wo_w  = (const float*)d_in[8];
    const float* wo_b  = (const float*)d_in[9];
    const float* fc1_w = (const float*)d_in[10];
    const float* fc1_b = (const float*)d_in[11];
    const float* fc2_w = (const float*)d_in[12];
    const float* fc2_b = (const float*)d_in[13];
    const float* ln1_g = (const float*)d_in[14];
    const float* ln1_b = (const float*)d_in[15];
    const float* ln2_g = (const float*)d_in[16];
    const float* ln2_b = (const float*)d_in[17];

    float *h1, *q, *k, *v, *ctx, *x1, *h2, *ff, *wr;
    cudaGetSymbolAddress((void**)&h1,  g_h1);
    cudaGetSymbolAddress((void**)&q,   g_q);
    cudaGetSymbolAddress((void**)&k,   g_k);
    cudaGetSymbolAddress((void**)&v,   g_v);
    cudaGetSymbolAddress((void**)&ctx, g_ctx);
    cudaGetSymbolAddress((void**)&x1,  g_x1);
    cudaGetSymbolAddress((void**)&h2,  g_h2);
    cudaGetSymbolAddress((void**)&ff,  g_ff);
    cudaGetSymbolAddress((void**)&wr,  g_wr);

    cudaFuncSetAttribute(mma_gemm<0>, cudaFuncAttributeMaxDynamicSharedMemorySize, GEMM_SMEM_BYTES);
    cudaFuncSetAttribute(mma_gemm<1>, cudaFuncAttributeMaxDynamicSharedMemorySize, GEMM_SMEM_BYTES);
    cudaFuncSetAttribute(mma_gemm<2>, cudaFuncAttributeMaxDynamicSharedMemorySize, GEMM_SMEM_BYTES);
    cudaFuncSetAttribute(attn_tc,     cudaFuncAttributeMaxDynamicSharedMemorySize, AT_SMEM);

    const int MM = 1024 * 1024;
    float* wr_q   = wr + 0 * MM;
    float* wr_k   = wr + 1 * MM;
    float* wr_v   = wr + 2 * MM;
    float* wr_o   = wr + 3 * MM;
    float* wr_fc1 = wr + 4 * MM;
    float* wr_fc2 = wr + 8 * MM;

    round_tf32_kernel<<<(1*MM/4 + 255)/256, 256>>>(wq_w,  wr_q,   1*MM/4);
    round_tf32_kernel<<<(1*MM/4 + 255)/256, 256>>>(wk_w,  wr_k,   1*MM/4);
    round_tf32_kernel<<<(1*MM/4 + 255)/256, 256>>>(wv_w,  wr_v,   1*MM/4);
    round_tf32_kernel<<<(1*MM/4 + 255)/256, 256>>>(wo_w,  wr_o,   1*MM/4);
    round_tf32_kernel<<<(4*MM/4 + 255)/256, 256>>>(fc1_w, wr_fc1, 4*MM/4);
    round_tf32_kernel<<<(4*MM/4 + 255)/256, 256>>>(fc2_w, wr_fc2, 4*MM/4);

    const dim3 gN1024(D_MODEL / 128, M_TOK / 128);  // (8, 32)
    const dim3 gN4096(D_FF    / 128, M_TOK / 128);  // (32, 32)

    // --- attention sub-block (pre-norm) ---
    ln_kernel<<<M_TOK, 256>>>(x, ln1_g, ln1_b, h1);
    mma_gemm<0><<<gN1024, 256, GEMM_SMEM_BYTES>>>(h1, wr_q, wq_b, nullptr, q, M_TOK, D_MODEL, D_MODEL);
    mma_gemm<0><<<gN1024, 256, GEMM_SMEM_BYTES>>>(h1, wr_k, wk_b, nullptr, k, M_TOK, D_MODEL, D_MODEL);
    mma_gemm<0><<<gN1024, 256, GEMM_SMEM_BYTES>>>(h1, wr_v, wv_b, nullptr, v, M_TOK, D_MODEL, D_MODEL);
    attn_tc<<<dim3(SEQ / 128, N_HEADS, BATCH), 128, AT_SMEM>>>(q, k, v, ctx);
    mma_gemm<2><<<gN1024, 256, GEMM_SMEM_BYTES>>>(ctx, wr_o, wo_b, x, x1, M_TOK, D_MODEL, D_MODEL);

    // --- FFN sub-block (pre-norm) ---
    ln_kernel<<<M_TOK, 256>>>(x1, ln2_g, ln2_b, h2);
    mma_gemm<1><<<gN4096, 256, GEMM_SMEM_BYTES>>>(h2, wr_fc1, fc1_b, nullptr, ff, M_TOK, D_FF, D_MODEL);
    mma_gemm<2><<<gN1024, 256, GEMM_SMEM_BYTES>>>(ff, wr_fc2, fc2_b, x1, (float*)d_out, M_TOK, D_MODEL, D_FF);
}

// round 5
// speedup vs baseline: 6.4105x; 1.5822x over previous
#include <cuda_runtime.h>
#include <cuda_fp16.h>
#include <math.h>
#include <stdint.h>

#define D_MODEL 1024
#define N_HEADS 16
#define HEAD_DIM 64
#define D_FF     4096
#define BATCH    2
#define SEQ      2048
#define M_TOK    (BATCH*SEQ)   /* 4096 token rows */

// ---------------- scratch (static device globals; no allocation) -------------
__device__ __half g_h1 [M_TOK*D_MODEL];
__device__ __half g_q  [M_TOK*D_MODEL];
__device__ __half g_k  [M_TOK*D_MODEL];
__device__ __half g_v  [M_TOK*D_MODEL];
__device__ __half g_ctx[M_TOK*D_MODEL];
__device__ __half g_h2 [M_TOK*D_MODEL];
__device__ __half g_ff [M_TOK*D_FF];
__device__ float  g_x1 [M_TOK*D_MODEL];
__device__ __half g_wh [12*1024*1024];   // fp16 weights

// ---------------- helpers -----------------------------------------------------
__device__ __forceinline__ void mma_f16(float* d, const uint32_t* a, const uint32_t* b) {
    asm volatile(
        "mma.sync.aligned.m16n8k16.row.col.f32.f16.f16.f32 "
        "{%0,%1,%2,%3}, {%4,%5,%6,%7}, {%8,%9}, {%0,%1,%2,%3};"
        : "+f"(d[0]), "+f"(d[1]), "+f"(d[2]), "+f"(d[3])
        : "r"(a[0]), "r"(a[1]), "r"(a[2]), "r"(a[3]), "r"(b[0]), "r"(b[1]));
}
__device__ __forceinline__ uint32_t smem_u32(const void* p) {
    uint32_t a;
    asm("{ .reg .u64 t; cvta.to.shared.u64 t, %1; cvt.u32.u64 %0, t; }" : "=r"(a) : "l"(p));
    return a;
}

// ---------------- LayerNorm (fp32 in -> fp16 out) -----------------------------
__device__ __forceinline__ float block_reduce_sum(float v, float* sh) {
    #pragma unroll
    for (int o = 16; o > 0; o >>= 1) v += __shfl_down_sync(0xFFFFFFFFu, v, o);
    int lane = threadIdx.x & 31, w = threadIdx.x >> 5;
    if (lane == 0) sh[w] = v;
    __syncthreads();
    if (w == 0) {
        v = (lane < 8) ? sh[lane] : 0.0f;
        #pragma unroll
        for (int o = 4; o > 0; o >>= 1) v += __shfl_down_sync(0xFFFFFFFFu, v, o);
        if (lane == 0) sh[0] = v;
    }
    __syncthreads();
    float r = sh[0];
    __syncthreads();
    return r;
}

__global__ void ln_kernel(const float* __restrict__ x,
                          const float* __restrict__ gamma,
                          const float* __restrict__ beta,
                          __half* __restrict__ out) {
    __shared__ float sh[32];
    const int row = blockIdx.x;
    const float* xr = x + (size_t)row * D_MODEL;
    float v[4];
    float s = 0.0f;
    #pragma unroll
    for (int i = 0; i < 4; i++) { v[i] = xr[threadIdx.x + i * 256]; s += v[i]; }
    float mean = block_reduce_sum(s, sh) * (1.0f / D_MODEL);
    float s2 = 0.0f;
    #pragma unroll
    for (int i = 0; i < 4; i++) { float d = v[i] - mean; s2 += d * d; }
    float var = block_reduce_sum(s2, sh) * (1.0f / D_MODEL);
    float rstd = rsqrtf(var + 1e-5f);
    __half* orow = out + (size_t)row * D_MODEL;
    #pragma unroll
    for (int i = 0; i < 4; i++) {
        int idx = threadIdx.x + i * 256;
        orow[idx] = __float2half_rn((v[i] - mean) * rstd * gamma[idx] + beta[idx]);
    }
}

// ---------------- weight -> fp16 conversion -----------------------------------
__global__ void tohalf_kernel(const float* __restrict__ in, __half* __restrict__ out, int n4) {
    int i = blockIdx.x * blockDim.x + threadIdx.x;
    if (i < n4) {
        float4 v = ((const float4*)in)[i];
        ((half2*)out)[i * 2]     = __floats2half2_rn(v.x, v.y);
        ((half2*)out)[i * 2 + 1] = __floats2half2_rn(v.z, v.w);
    }
}

// ---------------- FP16 mma.sync GEMM:  C[M,N] = A[M,K] @ W[N,K]^T -------------
// 128x128 tile, BK=32, 256 threads (8 warps, each 64x32 via m16n8k16),
// 2-stage cp.async double buffer, fp32 accumulators.
// Smem per stage: A[128][40] + W[128][40] halves (pad 8 -> conflict-free frags).
// EPI: 0 = +bias (half out); 1 = +bias, GELU (half out); 2 = +bias+residual (f32 out)
#define STG_H   (128*40)
#define STAGE_H (2*STG_H)
#define GEMM_SMEM_BYTES (2*STAGE_H*2 + 512)

__device__ __forceinline__ void load_chunk_h(
    __half* smem_h, const __half* __restrict__ A, const __half* __restrict__ W,
    int bm, int bn, int K, int c, int s, int tid) {
    __half* stage = smem_h + s * STAGE_H;
    #pragma unroll
    for (int it = 0; it < 4; it++) {
        int i = tid + it * 256;          // 0..1023
        bool isA = i < 512;
        int j = i & 511;
        int row = j >> 2, seg = j & 3;   // row 0..127, 16B seg 0..3
        __half* dst = stage + (isA ? 0 : STG_H) + row * 40 + seg * 8;
        const __half* src = (isA ? A + (size_t)(bm + row) * K
                                 : W + (size_t)(bn + row) * K) + c * 32 + seg * 8;
        asm volatile("cp.async.cg.shared.global [%0], [%1], 16;"
                     :: "r"(smem_u32(dst)), "l"(src));
    }
    asm volatile("cp.async.commit_group;" ::: "memory");
}

template<int EPI>
__global__ void __launch_bounds__(256, 2)
mma_gemm(const __half* __restrict__ A, const __half* __restrict__ W,
         const float* __restrict__ bias, const float* __restrict__ res,
         void* __restrict__ Cv, int M, int N, int K) {
    extern __shared__ char smem[];
    __half* smem_h = (__half*)smem;
    float*  sbias  = (float*)(smem + 2 * STAGE_H * 2);

    const int tid  = threadIdx.x;
    const int wid  = tid >> 5, lane = tid & 31;
    const int wm   = wid >> 2, wn = wid & 3;
    const int bm   = blockIdx.y * 128, bn = blockIdx.x * 128;
    const int NC   = K >> 5;

    if (tid < 128) sbias[tid] = bias[bn + tid];

    float acc[4][4][4];
    #pragma unroll
    for (int mt = 0; mt < 4; mt++)
        #pragma unroll
        for (int nt = 0; nt < 4; nt++)
            #pragma unroll
            for (int e = 0; e < 4; e++) acc[mt][nt][e] = 0.0f;

    load_chunk_h(smem_h, A, W, bm, bn, K, 0, 0, tid);

    const int lr4 = lane >> 2;
    const int lc  = lane & 3;

    for (int c = 0; c < NC; c++) {
        __syncthreads();
        if (c + 1 < NC) {
            load_chunk_h(smem_h, A, W, bm, bn, K, c + 1, (c + 1) & 1, tid);
            asm volatile("cp.async.wait_group 1;" ::: "memory");
        } else {
            asm volatile("cp.async.wait_group 0;" ::: "memory");
        }
        __syncthreads();

        const __half* As = smem_h + (c & 1) * STAGE_H;
        const __half* Ws = As + STG_H;

        #pragma unroll
        for (int ks = 0; ks < 2; ks++) {
            const int k0 = ks * 16 + lc * 2;
            uint32_t a[4][4], b[4][2];
            #pragma unroll
            for (int mt = 0; mt < 4; mt++) {
                const int r = wm * 64 + mt * 16 + lr4;
                a[mt][0] = *(const uint32_t*)&As[r * 40 + k0];
                a[mt][1] = *(const uint32_t*)&As[(r + 8) * 40 + k0];
                a[mt][2] = *(const uint32_t*)&As[r * 40 + k0 + 8];
                a[mt][3] = *(const uint32_t*)&As[(r + 8) * 40 + k0 + 8];
            }
            #pragma unroll
            for (int nt = 0; nt < 4; nt++) {
                const int nr = wn * 32 + nt * 8 + lr4;
                b[nt][0] = *(const uint32_t*)&Ws[nr * 40 + k0];
                b[nt][1] = *(const uint32_t*)&Ws[nr * 40 + k0 + 8];
            }
            #pragma unroll
            for (int mt = 0; mt < 4; mt++)
                #pragma unroll
                for (int nt = 0; nt < 4; nt++)
                    mma_f16(acc[mt][nt], a[mt], b[nt]);
        }
    }

    #pragma unroll
    for (int mt = 0; mt < 4; mt++) {
        const int row0 = bm + wm * 64 + mt * 16 + lr4;
        #pragma unroll
        for (int nt = 0; nt < 4; nt++) {
            const int coll = wn * 32 + nt * 8 + lc * 2;
            const int col  = bn + coll;
            #pragma unroll
            for (int half_i = 0; half_i < 2; half_i++) {
                const int row = row0 + half_i * 8;
                float ox = acc[mt][nt][half_i * 2 + 0] + sbias[coll];
                float oy = acc[mt][nt][half_i * 2 + 1] + sbias[coll + 1];
                if (EPI == 0) {
                    *(half2*)((__half*)Cv + (size_t)row * N + col) = __floats2half2_rn(ox, oy);
                } else if (EPI == 1) {
                    ox = 0.5f * ox * (1.0f + erff(ox * 0.70710678118654752f));
                    oy = 0.5f * oy * (1.0f + erff(oy * 0.70710678118654752f));
                    *(half2*)((__half*)Cv + (size_t)row * N + col) = __floats2half2_rn(ox, oy);
                } else {
                    const float2 rv = *(const float2*)(res + (size_t)row * N + col);
                    float2 o; o.x = ox + rv.x; o.y = oy + rv.y;
                    *(float2*)((float*)Cv + (size_t)row * N + col) = o;
                }
            }
        }
    }
}

// ---------------- Tensor-core causal flash attention (fp16 mma) ---------------
// CTA: 128 queries x 1 head. 4 warps x 32 q-rows. Key tiles of 64.
// Smem (halves): Q[128][72], K[64][72], Vt[64][72], P per-warp [32][72].
#define ATS 72
#define AT_SMEM ((128*ATS + 64*ATS + 64*ATS + 4*32*ATS)*2)

__global__ void __launch_bounds__(128)
attn_tc(const __half* __restrict__ Q, const __half* __restrict__ K,
        const __half* __restrict__ V, __half* __restrict__ O) {
    extern __shared__ __half smh[];
    __half* Qs  = smh;                       // [128][72]
    __half* Ks  = Qs + 128 * ATS;            // [64][72]
    __half* Vts = Ks + 64 * ATS;             // [64][72] (d-major)
    const int tid = threadIdx.x;
    const int wid = tid >> 5, lane = tid & 31;
    const int lr4 = lane >> 2, lc = lane & 3;
    __half* Ps = Vts + 64 * ATS + wid * 32 * ATS;   // per-warp [32][72]

    const int qb = blockIdx.x, h = blockIdx.y, b = blockIdx.z;
    const size_t qbase = ((size_t)(b * SEQ + qb * 128) * D_MODEL) + h * HEAD_DIM;

    // load Q tile, scale by 1/8 (exact in fp16)
    const half2 scl = __half2half2(__float2half(0.125f));
    #pragma unroll
    for (int it = 0; it < 8; it++) {
        const int i = tid + it * 128;
        const int row = i >> 3, seg = i & 7;          // 8 halves per seg
        const half2* src = (const half2*)(Q + qbase + (size_t)row * D_MODEL + seg * 8);
        half2* dst = (half2*)(Qs + row * ATS + seg * 8);
        #pragma unroll
        for (int j = 0; j < 4; j++) dst[j] = __hmul2(src[j], scl);
    }

    float m[4], l[4], acc[2][8][4];
    #pragma unroll
    for (int s = 0; s < 4; s++) { m[s] = -1e30f; l[s] = 0.0f; }
    #pragma unroll
    for (int mt = 0; mt < 2; mt++)
        #pragma unroll
        for (int nt = 0; nt < 8; nt++)
            #pragma unroll
            for (int e = 0; e < 4; e++) acc[mt][nt][e] = 0.0f;

    const int ntk = 2 * qb + 2;
    for (int kt = 0; kt < ntk; kt++) {
        __syncthreads();   // prior-iter reads done (covers Q store on iter 0)
        const size_t kbase = ((size_t)(b * SEQ + kt * 64) * D_MODEL) + h * HEAD_DIM;
        // K tile: raw copy via cp.async (64 rows x 128B = 512 x 16B)
        #pragma unroll
        for (int it = 0; it < 4; it++) {
            const int i = tid + it * 128;
            const int row = i >> 3, seg = i & 7;
            const __half* src = K + kbase + (size_t)row * D_MODEL + seg * 8;
            asm volatile("cp.async.cg.shared.global [%0], [%1], 16;"
                         :: "r"(smem_u32(Ks + row * ATS + seg * 8)), "l"(src));
        }
        asm volatile("cp.async.commit_group;" ::: "memory");
        // V tile transposed -> Vt[d][tok]
        {
            const int tok = tid >> 1, dbase = (tid & 1) * 32;
            const uint4* vp = (const uint4*)(V + kbase + (size_t)tok * D_MODEL + dbase);
            #pragma unroll
            for (int j = 0; j < 4; j++) {
                uint4 u = vp[j];
                const __half* hh = (const __half*)&u;
                const int d0 = dbase + j * 8;
                #pragma unroll
                for (int e = 0; e < 8; e++) Vts[(d0 + e) * ATS + tok] = hh[e];
            }
        }
        asm volatile("cp.async.wait_group 0;" ::: "memory");
        __syncthreads();

        // ---- S = Q @ K^T ----
        float s[2][8][4];
        #pragma unroll
        for (int mt = 0; mt < 2; mt++)
            #pragma unroll
            for (int nt = 0; nt < 8; nt++)
                #pragma unroll
                for (int e = 0; e < 4; e++) s[mt][nt][e] = 0.0f;

        #pragma unroll
        for (int ks = 0; ks < 4; ks++) {
            const int k0 = ks * 16 + lc * 2;
            uint32_t a[2][4];
            #pragma unroll
            for (int mt = 0; mt < 2; mt++) {
                const int r = wid * 32 + mt * 16 + lr4;
                a[mt][0] = *(const uint32_t*)&Qs[r * ATS + k0];
                a[mt][1] = *(const uint32_t*)&Qs[(r + 8) * ATS + k0];
                a[mt][2] = *(const uint32_t*)&Qs[r * ATS + k0 + 8];
                a[mt][3] = *(const uint32_t*)&Qs[(r + 8) * ATS + k0 + 8];
            }
            #pragma unroll
            for (int nt = 0; nt < 8; nt++) {
                uint32_t bb[2];
                const int nr = nt * 8 + lr4;
                bb[0] = *(const uint32_t*)&Ks[nr * ATS + k0];
                bb[1] = *(const uint32_t*)&Ks[nr * ATS + k0 + 8];
                mma_f16(s[0][nt], a[0], bb);
                mma_f16(s[1][nt], a[1], bb);
            }
        }

        // causal mask (diagonal-region tiles only)
        if (kt >= 2 * qb) {
            const int rbase = qb * 128 + wid * 32;
            #pragma unroll
            for (int mt = 0; mt < 2; mt++) {
                const int row0 = rbase + mt * 16 + lr4;
                #pragma unroll
                for (int nt = 0; nt < 8; nt++) {
                    const int col0 = kt * 64 + nt * 8 + 2 * lc;
                    if (col0     > row0)     s[mt][nt][0] = -1e9f;
                    if (col0 + 1 > row0)     s[mt][nt][1] = -1e9f;
                    if (col0     > row0 + 8) s[mt][nt][2] = -1e9f;
                    if (col0 + 1 > row0 + 8) s[mt][nt][3] = -1e9f;
                }
            }
        }

        // ---- online softmax (fp32) ----
        #pragma unroll
        for (int mt = 0; mt < 2; mt++)
            #pragma unroll
            for (int hf = 0; hf < 2; hf++) {
                const int slot = mt * 2 + hf;
                float mx = m[slot];
                #pragma unroll
                for (int nt = 0; nt < 8; nt++)
                    mx = fmaxf(mx, fmaxf(s[mt][nt][hf * 2], s[mt][nt][hf * 2 + 1]));
                mx = fmaxf(mx, __shfl_xor_sync(0xFFFFFFFFu, mx, 1));
                mx = fmaxf(mx, __shfl_xor_sync(0xFFFFFFFFu, mx, 2));
                const float corr = __expf(m[slot] - mx);
                m[slot] = mx;
                float sum = 0.0f;
                #pragma unroll
                for (int nt = 0; nt < 8; nt++) {
                    float p0 = __expf(s[mt][nt][hf * 2]     - mx);
                    float p1 = __expf(s[mt][nt][hf * 2 + 1] - mx);
                    s[mt][nt][hf * 2] = p0; s[mt][nt][hf * 2 + 1] = p1;
                    sum += p0 + p1;
                }
                sum += __shfl_xor_sync(0xFFFFFFFFu, sum, 1);
                sum += __shfl_xor_sync(0xFFFFFFFFu, sum, 2);
                l[slot] = l[slot] * corr + sum;
                #pragma unroll
                for (int nt = 0; nt < 8; nt++) {
                    acc[mt][nt][hf * 2]     *= corr;
                    acc[mt][nt][hf * 2 + 1] *= corr;
                }
            }

        // ---- stage P (fp16) ----
        #pragma unroll
        for (int mt = 0; mt < 2; mt++)
            #pragma unroll
            for (int nt = 0; nt < 8; nt++) {
                *(half2*)(Ps + (mt * 16 + lr4) * ATS + nt * 8 + 2 * lc) =
                    __floats2half2_rn(s[mt][nt][0], s[mt][nt][1]);
                *(half2*)(Ps + (mt * 16 + lr4 + 8) * ATS + nt * 8 + 2 * lc) =
                    __floats2half2_rn(s[mt][nt][2], s[mt][nt][3]);
            }
        __syncwarp();

        // ---- O += P @ V ----
        #pragma unroll
        for (int ks = 0; ks < 4; ks++) {
            const int k0 = ks * 16 + lc * 2;
            uint32_t a[2][4];
            #pragma unroll
            for (int mt = 0; mt < 2; mt++) {
                const int r = mt * 16 + lr4;
                a[mt][0] = *(const uint32_t*)&Ps[r * ATS + k0];
                a[mt][1] = *(const uint32_t*)&Ps[(r + 8) * ATS + k0];
                a[mt][2] = *(const uint32_t*)&Ps[r * ATS + k0 + 8];
                a[mt][3] = *(const uint32_t*)&Ps[(r + 8) * ATS + k0 + 8];
            }
            #pragma unroll
            for (int nt = 0; nt < 8; nt++) {
                uint32_t bb[2];
                const int nr = nt * 8 + lr4;
                bb[0] = *(const uint32_t*)&Vts[nr * ATS + k0];
                bb[1] = *(const uint32_t*)&Vts[nr * ATS + k0 + 8];
                mma_f16(acc[0][nt], a[0], bb);
                mma_f16(acc[1][nt], a[1], bb);
            }
        }
        __syncwarp();
    }

    // ---- epilogue: O = acc / l (fp16 out, feeds Wo GEMM) ----
    float inv[4];
    #pragma unroll
    for (int s = 0; s < 4; s++) inv[s] = 1.0f / l[s];
    #pragma unroll
    for (int mt = 0; mt < 2; mt++) {
        const int row0 = qb * 128 + wid * 32 + mt * 16 + lr4;
        #pragma unroll
        for (int nt = 0; nt < 8; nt++) {
            const int col = h * HEAD_DIM + nt * 8 + 2 * lc;
            *(half2*)(O + (size_t)(b * SEQ + row0) * D_MODEL + col) =
                __floats2half2_rn(acc[mt][nt][0] * inv[mt * 2], acc[mt][nt][1] * inv[mt * 2]);
            *(half2*)(O + (size_t)(b * SEQ + row0 + 8) * D_MODEL + col) =
                __floats2half2_rn(acc[mt][nt][2] * inv[mt * 2 + 1], acc[mt][nt][3] * inv[mt * 2 + 1]);
        }
    }
}

// ---------------- launch ------------------------------------------------------
extern "C" void kernel_launch(void* const* d_in, const int* in_sizes, int n_in,
                              void* d_out, int out_size) {
    const float* x     = (const float*)d_in[0];
    const float* wq_w  = (const float*)d_in[2];
    const float* wq_b  = (const float*)d_in[3];
    const float* wk_w  = (const float*)d_in[4];
    const float* wk_b  = (const float*)d_in[5];
    const float* wv_w  = (const float*)d_in[6];
    const float* wv_b  = (const float*)d_in[7];
    const float* wo_w  = (const float*)d_in[8];
    const float* wo_b  = (const float*)d_in[9];
    const float* fc1_w = (const float*)d_in[10];
    const float* fc1_b = (const float*)d_in[11];
    const float* fc2_w = (const float*)d_in[12];
    const float* fc2_b = (const float*)d_in[13];
    const float* ln1_g = (const float*)d_in[14];
    const float* ln1_b = (const float*)d_in[15];
    const float* ln2_g = (const float*)d_in[16];
    const float* ln2_b = (const float*)d_in[17];

    __half *h1, *q, *k, *v, *ctx, *h2, *ff, *wh;
    float *x1;
    cudaGetSymbolAddress((void**)&h1,  g_h1);
    cudaGetSymbolAddress((void**)&q,   g_q);
    cudaGetSymbolAddress((void**)&k,   g_k);
    cudaGetSymbolAddress((void**)&v,   g_v);
    cudaGetSymbolAddress((void**)&ctx, g_ctx);
    cudaGetSymbolAddress((void**)&h2,  g_h2);
    cudaGetSymbolAddress((void**)&ff,  g_ff);
    cudaGetSymbolAddress((void**)&x1,  g_x1);
    cudaGetSymbolAddress((void**)&wh,  g_wh);

    cudaFuncSetAttribute(mma_gemm<0>, cudaFuncAttributeMaxDynamicSharedMemorySize, GEMM_SMEM_BYTES);
    cudaFuncSetAttribute(mma_gemm<1>, cudaFuncAttributeMaxDynamicSharedMemorySize, GEMM_SMEM_BYTES);
    cudaFuncSetAttribute(mma_gemm<2>, cudaFuncAttributeMaxDynamicSharedMemorySize, GEMM_SMEM_BYTES);
    cudaFuncSetAttribute(attn_tc,     cudaFuncAttributeMaxDynamicSharedMemorySize, AT_SMEM);

    const int MM = 1024 * 1024;
    __half* wh_q   = wh + 0 * MM;
    __half* wh_k   = wh + 1 * MM;
    __half* wh_v   = wh + 2 * MM;
    __half* wh_o   = wh + 3 * MM;
    __half* wh_fc1 = wh + 4 * MM;
    __half* wh_fc2 = wh + 8 * MM;

    tohalf_kernel<<<(1*MM/4 + 255)/256, 256>>>(wq_w,  wh_q,   1*MM/4);
    tohalf_kernel<<<(1*MM/4 + 255)/256, 256>>>(wk_w,  wh_k,   1*MM/4);
    tohalf_kernel<<<(1*MM/4 + 255)/256, 256>>>(wv_w,  wh_v,   1*MM/4);
    tohalf_kernel<<<(1*MM/4 + 255)/256, 256>>>(wo_w,  wh_o,   1*MM/4);
    tohalf_kernel<<<(4*MM/4 + 255)/256, 256>>>(fc1_w, wh_fc1, 4*MM/4);
    tohalf_kernel<<<(4*MM/4 + 255)/256, 256>>>(fc2_w, wh_fc2, 4*MM/4);

    const dim3 gN1024(D_MODEL / 128, M_TOK / 128);  // (8, 32)
    const dim3 gN4096(D_FF    / 128, M_TOK / 128);  // (32, 32)

    // --- attention sub-block (pre-norm) ---
    ln_kernel<<<M_TOK, 256>>>(x, ln1_g, ln1_b, h1);
    mma_gemm<0><<<gN1024, 256, GEMM_SMEM_BYTES>>>(h1, wh_q, wq_b, nullptr, q, M_TOK, D_MODEL, D_MODEL);
    mma_gemm<0><<<gN1024, 256, GEMM_SMEM_BYTES>>>(h1, wh_k, wk_b, nullptr, k, M_TOK, D_MODEL, D_MODEL);
    mma_gemm<0><<<gN1024, 256, GEMM_SMEM_BYTES>>>(h1, wh_v, wv_b, nullptr, v, M_TOK, D_MODEL, D_MODEL);
    attn_tc<<<dim3(SEQ / 128, N_HEADS, BATCH), 128, AT_SMEM>>>(q, k, v, ctx);
    mma_gemm<2><<<gN1024, 256, GEMM_SMEM_BYTES>>>(ctx, wh_o, wo_b, x, x1, M_TOK, D_MODEL, D_MODEL);

    // --- FFN sub-block (pre-norm) ---
    ln_kernel<<<M_TOK, 256>>>(x1, ln2_g, ln2_b, h2);
    mma_gemm<1><<<gN4096, 256, GEMM_SMEM_BYTES>>>(h2, wh_fc1, fc1_b, nullptr, ff, M_TOK, D_FF, D_MODEL);
    mma_gemm<2><<<gN1024, 256, GEMM_SMEM_BYTES>>>(ff, wh_fc2, fc2_b, x1, d_out, M_TOK, D_MODEL, D_FF);
}

// round 7
// speedup vs baseline: 7.0717x; 1.1031x over previous
#include <cuda_runtime.h>
#include <cuda_fp16.h>
#include <math.h>
#include <stdint.h>

#define D_MODEL 1024
#define N_HEADS 16
#define HEAD_DIM 64
#define D_FF     4096
#define BATCH    2
#define SEQ      2048
#define M_TOK    (BATCH*SEQ)   /* 4096 token rows */

// ---------------- scratch (static device globals; no allocation) -------------
__device__ __half g_h1 [M_TOK*D_MODEL];
__device__ __half g_qkv[3*M_TOK*D_MODEL];
__device__ __half g_ctx[M_TOK*D_MODEL];
__device__ __half g_h2 [M_TOK*D_MODEL];
__device__ __half g_ff [M_TOK*D_FF];
__device__ float  g_x1 [M_TOK*D_MODEL];
__device__ __half g_wh [12*1024*1024];   // fp16 weights: q,k,v,o,fc1,fc2

// ---------------- helpers -----------------------------------------------------
__device__ __forceinline__ void mma_f16(float* d, const uint32_t* a, const uint32_t* b) {
    asm volatile(
        "mma.sync.aligned.m16n8k16.row.col.f32.f16.f16.f32 "
        "{%0,%1,%2,%3}, {%4,%5,%6,%7}, {%8,%9}, {%0,%1,%2,%3};"
        : "+f"(d[0]), "+f"(d[1]), "+f"(d[2]), "+f"(d[3])
        : "r"(a[0]), "r"(a[1]), "r"(a[2]), "r"(a[3]), "r"(b[0]), "r"(b[1]));
}
__device__ __forceinline__ void ldsm_x4(uint32_t* r, uint32_t addr) {
    asm volatile("ldmatrix.sync.aligned.m8n8.x4.shared.b16 {%0,%1,%2,%3}, [%4];"
                 : "=r"(r[0]), "=r"(r[1]), "=r"(r[2]), "=r"(r[3]) : "r"(addr));
}
__device__ __forceinline__ uint32_t smem_u32(const void* p) {
    uint32_t a;
    asm("{ .reg .u64 t; cvta.to.shared.u64 t, %1; cvt.u32.u64 %0, t; }" : "=r"(a) : "l"(p));
    return a;
}

// ---------------- LayerNorm (fp32 in -> fp16 out) -----------------------------
__device__ __forceinline__ float block_reduce_sum(float v, float* sh) {
    #pragma unroll
    for (int o = 16; o > 0; o >>= 1) v += __shfl_down_sync(0xFFFFFFFFu, v, o);
    int lane = threadIdx.x & 31, w = threadIdx.x >> 5;
    if (lane == 0) sh[w] = v;
    __syncthreads();
    if (w == 0) {
        v = (lane < 8) ? sh[lane] : 0.0f;
        #pragma unroll
        for (int o = 4; o > 0; o >>= 1) v += __shfl_down_sync(0xFFFFFFFFu, v, o);
        if (lane == 0) sh[0] = v;
    }
    __syncthreads();
    float r = sh[0];
    __syncthreads();
    return r;
}

__global__ void ln_kernel(const float* __restrict__ x,
                          const float* __restrict__ gamma,
                          const float* __restrict__ beta,
                          __half* __restrict__ out) {
    __shared__ float sh[32];
    const int row = blockIdx.x;
    const float* xr = x + (size_t)row * D_MODEL;
    float v[4];
    float s = 0.0f;
    #pragma unroll
    for (int i = 0; i < 4; i++) { v[i] = xr[threadIdx.x + i * 256]; s += v[i]; }
    float mean = block_reduce_sum(s, sh) * (1.0f / D_MODEL);
    float s2 = 0.0f;
    #pragma unroll
    for (int i = 0; i < 4; i++) { float d = v[i] - mean; s2 += d * d; }
    float var = block_reduce_sum(s2, sh) * (1.0f / D_MODEL);
    float rstd = rsqrtf(var + 1e-5f);
    __half* orow = out + (size_t)row * D_MODEL;
    #pragma unroll
    for (int i = 0; i < 4; i++) {
        int idx = threadIdx.x + i * 256;
        orow[idx] = __float2half_rn((v[i] - mean) * rstd * gamma[idx] + beta[idx]);
    }
}

// ---------------- all-weights -> fp16 conversion (one launch) -----------------
__global__ void tohalf_all(const float* __restrict__ w0, const float* __restrict__ w1,
                           const float* __restrict__ w2, const float* __restrict__ w3,
                           const float* __restrict__ w4, const float* __restrict__ w5,
                           __half* __restrict__ out) {
    const int Q4 = 256 * 1024;           // 1M floats in float4 units
    int i = blockIdx.x * blockDim.x + threadIdx.x;   // float4 index, [0, 3M)
    const float* src; int base;
    if      (i <     Q4) { src = w0; base = 0;      }
    else if (i < 2 * Q4) { src = w1; base = Q4;     }
    else if (i < 3 * Q4) { src = w2; base = 2 * Q4; }
    else if (i < 4 * Q4) { src = w3; base = 3 * Q4; }
    else if (i < 8 * Q4) { src = w4; base = 4 * Q4; }
    else                 { src = w5; base = 8 * Q4; }
    float4 v = ((const float4*)src)[i - base];
    ((half2*)out)[i * 2]     = __floats2half2_rn(v.x, v.y);
    ((half2*)out)[i * 2 + 1] = __floats2half2_rn(v.z, v.w);
}

// ---------------- FP16 mma.sync GEMM:  C[M,N] = A[M,K] @ W[N,K]^T -------------
// 128x128 tile, BK=32, 256 threads (8 warps, each 64x32), ldmatrix fragments,
// 4-stage cp.async pipeline (1 sync per chunk), fp32 accumulators.
// EPI: 0 = +bias (half out); 1 = +bias+GELU (half out); 2 = +bias+res (f32 out);
//      3 = QKV: split output across 3 contiguous [M,1024] matrices, bias select.
#define STG_H   (128*40)
#define STAGE_H (2*STG_H)
#define NSTAGE  4
#define GEMM_SMEM_BYTES (NSTAGE*STAGE_H*2 + 512)

__device__ __forceinline__ void load_chunk_h(
    __half* smem_h, const __half* __restrict__ A, const __half* __restrict__ W,
    int bm, int bn, int K, int c, int tid) {
    __half* stage = smem_h + (c & (NSTAGE - 1)) * STAGE_H;
    #pragma unroll
    for (int it = 0; it < 4; it++) {
        int i = tid + it * 256;          // 0..1023
        bool isA = i < 512;
        int j = i & 511;
        int row = j >> 2, seg = j & 3;   // row 0..127, 16B seg 0..3
        __half* dst = stage + (isA ? 0 : STG_H) + row * 40 + seg * 8;
        const __half* src = (isA ? A + (size_t)(bm + row) * K
                                 : W + (size_t)(bn + row) * K) + c * 32 + seg * 8;
        asm volatile("cp.async.cg.shared.global [%0], [%1], 16;"
                     :: "r"(smem_u32(dst)), "l"(src));
    }
    asm volatile("cp.async.commit_group;" ::: "memory");
}

template<int EPI>
__global__ void __launch_bounds__(256, 2)
mma_gemm(const __half* __restrict__ A, const __half* __restrict__ W,
         const float* __restrict__ b0, const float* __restrict__ b1,
         const float* __restrict__ b2, const float* __restrict__ res,
         void* __restrict__ Cv, int M, int N, int K) {
    extern __shared__ char smem[];
    __half* smem_h = (__half*)smem;
    float*  sbias  = (float*)(smem + NSTAGE * STAGE_H * 2);

    const int tid  = threadIdx.x;
    const int wid  = tid >> 5, lane = tid & 31;
    const int wm   = wid >> 2, wn = wid & 3;
    const int bm   = blockIdx.y * 128, bn = blockIdx.x * 128;
    const int NC   = K >> 5;

    // bias (with QKV selection)
    const float* bsel = b0;
    int bcol = bn;
    if (EPI == 3) {
        const int which = bn >> 10;
        bsel = (which == 0) ? b0 : (which == 1) ? b1 : b2;
        bcol = bn & 1023;
    }
    if (tid < 128) sbias[tid] = bsel[bcol + tid];

    float acc[4][4][4];
    #pragma unroll
    for (int mt = 0; mt < 4; mt++)
        #pragma unroll
        for (int nt = 0; nt < 4; nt++)
            #pragma unroll
            for (int e = 0; e < 4; e++) acc[mt][nt][e] = 0.0f;

    // prologue: stages 0..2
    load_chunk_h(smem_h, A, W, bm, bn, K, 0, tid);
    load_chunk_h(smem_h, A, W, bm, bn, K, 1, tid);
    load_chunk_h(smem_h, A, W, bm, bn, K, 2, tid);

    // per-thread ldmatrix byte offsets
    const int g = lane >> 3, r8 = lane & 7;
    const uint32_t sb = smem_u32(smem_h);
    const uint32_t aBase = sb + ((wm * 64 + (g & 1) * 8 + r8) * 40 + (g >> 1) * 8) * 2;
    const uint32_t bBase = sb + (STG_H + (wn * 32 + (g >> 1) * 8 + r8) * 40 + (g & 1) * 8) * 2;

    for (int c = 0; c < NC; c++) {
        // wait for chunk c (outstanding-after-c = min(NC-1-c, 2))
        const int rem = NC - 1 - c;
        if (rem >= 2)      asm volatile("cp.async.wait_group 2;" ::: "memory");
        else if (rem == 1) asm volatile("cp.async.wait_group 1;" ::: "memory");
        else               asm volatile("cp.async.wait_group 0;" ::: "memory");
        __syncthreads();   // chunk c visible to all; all done computing chunk c-1

        if (c + 3 < NC) load_chunk_h(smem_h, A, W, bm, bn, K, c + 3, tid);

        const uint32_t stOff = (uint32_t)(c & (NSTAGE - 1)) * (STAGE_H * 2);
        #pragma unroll
        for (int ks = 0; ks < 2; ks++) {
            uint32_t a[4][4], b[2][4];
            #pragma unroll
            for (int mt = 0; mt < 4; mt++)
                ldsm_x4(a[mt], aBase + stOff + mt * (16 * 40 * 2) + ks * 32);
            #pragma unroll
            for (int ntp = 0; ntp < 2; ntp++)
                ldsm_x4(b[ntp], bBase + stOff + ntp * (16 * 40 * 2) + ks * 32);
            #pragma unroll
            for (int mt = 0; mt < 4; mt++)
                #pragma unroll
                for (int nt = 0; nt < 4; nt++)
                    mma_f16(acc[mt][nt], a[mt], &b[nt >> 1][(nt & 1) * 2]);
        }
    }

    // ---- epilogue ----
    const int lr4 = lane >> 2, lc = lane & 3;
    const int cstride = (EPI == 3) ? 1024 : N;
    __half* Ch = (__half*)Cv;
    if (EPI == 3) Ch += (size_t)(bn >> 10) * M_TOK * 1024;
    const int cbn = (EPI == 3) ? (bn & 1023) : bn;

    #pragma unroll
    for (int mt = 0; mt < 4; mt++) {
        const int row0 = bm + wm * 64 + mt * 16 + lr4;
        #pragma unroll
        for (int nt = 0; nt < 4; nt++) {
            const int coll = wn * 32 + nt * 8 + lc * 2;
            const int col  = cbn + coll;
            #pragma unroll
            for (int half_i = 0; half_i < 2; half_i++) {
                const int row = row0 + half_i * 8;
                float ox = acc[mt][nt][half_i * 2 + 0] + sbias[coll];
                float oy = acc[mt][nt][half_i * 2 + 1] + sbias[coll + 1];
                if (EPI == 0 || EPI == 3) {
                    *(half2*)(Ch + (size_t)row * cstride + col) = __floats2half2_rn(ox, oy);
                } else if (EPI == 1) {
                    ox = 0.5f * ox * (1.0f + erff(ox * 0.70710678118654752f));
                    oy = 0.5f * oy * (1.0f + erff(oy * 0.70710678118654752f));
                    *(half2*)(Ch + (size_t)row * cstride + col) = __floats2half2_rn(ox, oy);
                } else {
                    const float2 rv = *(const float2*)(res + (size_t)row * N + col);
                    float2 o; o.x = ox + rv.x; o.y = oy + rv.y;
                    *(float2*)((float*)Cv + (size_t)row * N + col) = o;
                }
            }
        }
    }
}

// ---------------- Tensor-core causal flash attention (fp16 mma) ---------------
#define ATS 72
#define AT_SMEM ((128*ATS + 64*ATS + 64*ATS + 4*32*ATS)*2)

__global__ void __launch_bounds__(128)
attn_tc(const __half* __restrict__ Q, const __half* __restrict__ K,
        const __half* __restrict__ V, __half* __restrict__ O) {
    extern __shared__ __half smh[];
    __half* Qs  = smh;                       // [128][72]
    __half* Ks  = Qs + 128 * ATS;            // [64][72]
    __half* Vts = Ks + 64 * ATS;             // [64][72] (d-major)
    const int tid = threadIdx.x;
    const int wid = tid >> 5, lane = tid & 31;
    const int lr4 = lane >> 2, lc = lane & 3;
    __half* Ps = Vts + 64 * ATS + wid * 32 * ATS;   // per-warp [32][72]

    const int qb = blockIdx.x, h = blockIdx.y, b = blockIdx.z;
    const size_t qbase = ((size_t)(b * SEQ + qb * 128) * D_MODEL) + h * HEAD_DIM;

    const half2 scl = __half2half2(__float2half(0.125f));
    #pragma unroll
    for (int it = 0; it < 8; it++) {
        const int i = tid + it * 128;
        const int row = i >> 3, seg = i & 7;
        const half2* src = (const half2*)(Q + qbase + (size_t)row * D_MODEL + seg * 8);
        half2* dst = (half2*)(Qs + row * ATS + seg * 8);
        #pragma unroll
        for (int j = 0; j < 4; j++) dst[j] = __hmul2(src[j], scl);
    }

    float m[4], l[4], acc[2][8][4];
    #pragma unroll
    for (int s = 0; s < 4; s++) { m[s] = -1e30f; l[s] = 0.0f; }
    #pragma unroll
    for (int mt = 0; mt < 2; mt++)
        #pragma unroll
        for (int nt = 0; nt < 8; nt++)
            #pragma unroll
            for (int e = 0; e < 4; e++) acc[mt][nt][e] = 0.0f;

    const int ntk = 2 * qb + 2;
    for (int kt = 0; kt < ntk; kt++) {
        __syncthreads();
        const size_t kbase = ((size_t)(b * SEQ + kt * 64) * D_MODEL) + h * HEAD_DIM;
        #pragma unroll
        for (int it = 0; it < 4; it++) {
            const int i = tid + it * 128;
            const int row = i >> 3, seg = i & 7;
            const __half* src = K + kbase + (size_t)row * D_MODEL + seg * 8;
            asm volatile("cp.async.cg.shared.global [%0], [%1], 16;"
                         :: "r"(smem_u32(Ks + row * ATS + seg * 8)), "l"(src));
        }
        asm volatile("cp.async.commit_group;" ::: "memory");
        {
            const int tok = tid >> 1, dbase = (tid & 1) * 32;
            const uint4* vp = (const uint4*)(V + kbase + (size_t)tok * D_MODEL + dbase);
            #pragma unroll
            for (int j = 0; j < 4; j++) {
                uint4 u = vp[j];
                const __half* hh = (const __half*)&u;
                const int d0 = dbase + j * 8;
                #pragma unroll
                for (int e = 0; e < 8; e++) Vts[(d0 + e) * ATS + tok] = hh[e];
            }
        }
        asm volatile("cp.async.wait_group 0;" ::: "memory");
        __syncthreads();

        float s[2][8][4];
        #pragma unroll
        for (int mt = 0; mt < 2; mt++)
            #pragma unroll
            for (int nt = 0; nt < 8; nt++)
                #pragma unroll
                for (int e = 0; e < 4; e++) s[mt][nt][e] = 0.0f;

        #pragma unroll
        for (int ks = 0; ks < 4; ks++) {
            const int k0 = ks * 16 + lc * 2;
            uint32_t a[2][4];
            #pragma unroll
            for (int mt = 0; mt < 2; mt++) {
                const int r = wid * 32 + mt * 16 + lr4;
                a[mt][0] = *(const uint32_t*)&Qs[r * ATS + k0];
                a[mt][1] = *(const uint32_t*)&Qs[(r + 8) * ATS + k0];
                a[mt][2] = *(const uint32_t*)&Qs[r * ATS + k0 + 8];
                a[mt][3] = *(const uint32_t*)&Qs[(r + 8) * ATS + k0 + 8];
            }
            #pragma unroll
            for (int nt = 0; nt < 8; nt++) {
                uint32_t bb[2];
                const int nr = nt * 8 + lr4;
                bb[0] = *(const uint32_t*)&Ks[nr * ATS + k0];
                bb[1] = *(const uint32_t*)&Ks[nr * ATS + k0 + 8];
                mma_f16(s[0][nt], a[0], bb);
                mma_f16(s[1][nt], a[1], bb);
            }
        }

        if (kt >= 2 * qb) {
            const int rbase = qb * 128 + wid * 32;
            #pragma unroll
            for (int mt = 0; mt < 2; mt++) {
                const int row0 = rbase + mt * 16 + lr4;
                #pragma unroll
                for (int nt = 0; nt < 8; nt++) {
                    const int col0 = kt * 64 + nt * 8 + 2 * lc;
                    if (col0     > row0)     s[mt][nt][0] = -1e9f;
                    if (col0 + 1 > row0)     s[mt][nt][1] = -1e9f;
                    if (col0     > row0 + 8) s[mt][nt][2] = -1e9f;
                    if (col0 + 1 > row0 + 8) s[mt][nt][3] = -1e9f;
                }
            }
        }

        #pragma unroll
        for (int mt = 0; mt < 2; mt++)
            #pragma unroll
            for (int hf = 0; hf < 2; hf++) {
                const int slot = mt * 2 + hf;
                float mx = m[slot];
                #pragma unroll
                for (int nt = 0; nt < 8; nt++)
                    mx = fmaxf(mx, fmaxf(s[mt][nt][hf * 2], s[mt][nt][hf * 2 + 1]));
                mx = fmaxf(mx, __shfl_xor_sync(0xFFFFFFFFu, mx, 1));
                mx = fmaxf(mx, __shfl_xor_sync(0xFFFFFFFFu, mx, 2));
                const float corr = __expf(m[slot] - mx);
                m[slot] = mx;
                float sum = 0.0f;
                #pragma unroll
                for (int nt = 0; nt < 8; nt++) {
                    float p0 = __expf(s[mt][nt][hf * 2]     - mx);
                    float p1 = __expf(s[mt][nt][hf * 2 + 1] - mx);
                    s[mt][nt][hf * 2] = p0; s[mt][nt][hf * 2 + 1] = p1;
                    sum += p0 + p1;
                }
                sum += __shfl_xor_sync(0xFFFFFFFFu, sum, 1);
                sum += __shfl_xor_sync(0xFFFFFFFFu, sum, 2);
                l[slot] = l[slot] * corr + sum;
                #pragma unroll
                for (int nt = 0; nt < 8; nt++) {
                    acc[mt][nt][hf * 2]     *= corr;
                    acc[mt][nt][hf * 2 + 1] *= corr;
                }
            }

        #pragma unroll
        for (int mt = 0; mt < 2; mt++)
            #pragma unroll
            for (int nt = 0; nt < 8; nt++) {
                *(half2*)(Ps + (mt * 16 + lr4) * ATS + nt * 8 + 2 * lc) =
                    __floats2half2_rn(s[mt][nt][0], s[mt][nt][1]);
                *(half2*)(Ps + (mt * 16 + lr4 + 8) * ATS + nt * 8 + 2 * lc) =
                    __floats2half2_rn(s[mt][nt][2], s[mt][nt][3]);
            }
        __syncwarp();

        #pragma unroll
        for (int ks = 0; ks < 4; ks++) {
            const int k0 = ks * 16 + lc * 2;
            uint32_t a[2][4];
            #pragma unroll
            for (int mt = 0; mt < 2; mt++) {
                const int r = mt * 16 + lr4;
                a[mt][0] = *(const uint32_t*)&Ps[r * ATS + k0];
                a[mt][1] = *(const uint32_t*)&Ps[(r + 8) * ATS + k0];
                a[mt][2] = *(const uint32_t*)&Ps[r * ATS + k0 + 8];
                a[mt][3] = *(const uint32_t*)&Ps[(r + 8) * ATS + k0 + 8];
            }
            #pragma unroll
            for (int nt = 0; nt < 8; nt++) {
                uint32_t bb[2];
                const int nr = nt * 8 + lr4;
                bb[0] = *(const uint32_t*)&Vts[nr * ATS + k0];
                bb[1] = *(const uint32_t*)&Vts[nr * ATS + k0 + 8];
                mma_f16(acc[0][nt], a[0], bb);
                mma_f16(acc[1][nt], a[1], bb);
            }
        }
        __syncwarp();
    }

    float inv[4];
    #pragma unroll
    for (int s = 0; s < 4; s++) inv[s] = 1.0f / l[s];
    #pragma unroll
    for (int mt = 0; mt < 2; mt++) {
        const int row0 = qb * 128 + wid * 32 + mt * 16 + lr4;
        #pragma unroll
        for (int nt = 0; nt < 8; nt++) {
            const int col = h * HEAD_DIM + nt * 8 + 2 * lc;
            *(half2*)(O + (size_t)(b * SEQ + row0) * D_MODEL + col) =
                __floats2half2_rn(acc[mt][nt][0] * inv[mt * 2], acc[mt][nt][1] * inv[mt * 2]);
            *(half2*)(O + (size_t)(b * SEQ + row0 + 8) * D_MODEL + col) =
                __floats2half2_rn(acc[mt][nt][2] * inv[mt * 2 + 1], acc[mt][nt][3] * inv[mt * 2 + 1]);
        }
    }
}

// ---------------- launch ------------------------------------------------------
extern "C" void kernel_launch(void* const* d_in, const int* in_sizes, int n_in,
                              void* d_out, int out_size) {
    const float* x     = (const float*)d_in[0];
    const float* wq_w  = (const float*)d_in[2];
    const float* wq_b  = (const float*)d_in[3];
    const float* wk_w  = (const float*)d_in[4];
    const float* wk_b  = (const float*)d_in[5];
    const float* wv_w  = (const float*)d_in[6];
    const float* wv_b  = (const float*)d_in[7];
    const float* wo_w  = (const float*)d_in[8];
    const float* wo_b  = (const float*)d_in[9];
    const float* fc1_w = (const float*)d_in[10];
    const float* fc1_b = (const float*)d_in[11];
    const float* fc2_w = (const float*)d_in[12];
    const float* fc2_b = (const float*)d_in[13];
    const float* ln1_g = (const float*)d_in[14];
    const float* ln1_b = (const float*)d_in[15];
    const float* ln2_g = (const float*)d_in[16];
    const float* ln2_b = (const float*)d_in[17];

    __half *h1, *qkv, *ctx, *h2, *ff, *wh;
    float *x1;
    cudaGetSymbolAddress((void**)&h1,  g_h1);
    cudaGetSymbolAddress((void**)&qkv, g_qkv);
    cudaGetSymbolAddress((void**)&ctx, g_ctx);
    cudaGetSymbolAddress((void**)&h2,  g_h2);
    cudaGetSymbolAddress((void**)&ff,  g_ff);
    cudaGetSymbolAddress((void**)&x1,  g_x1);
    cudaGetSymbolAddress((void**)&wh,  g_wh);

    cudaFuncSetAttribute(mma_gemm<1>, cudaFuncAttributeMaxDynamicSharedMemorySize, GEMM_SMEM_BYTES);
    cudaFuncSetAttribute(mma_gemm<2>, cudaFuncAttributeMaxDynamicSharedMemorySize, GEMM_SMEM_BYTES);
    cudaFuncSetAttribute(mma_gemm<3>, cudaFuncAttributeMaxDynamicSharedMemorySize, GEMM_SMEM_BYTES);
    cudaFuncSetAttribute(attn_tc,     cudaFuncAttributeMaxDynamicSharedMemorySize, AT_SMEM);

    const int MM = 1024 * 1024;
    __half* wh_qkv = wh;             // q,k,v contiguous [3072,1024]
    __half* wh_o   = wh + 3 * MM;
    __half* wh_fc1 = wh + 4 * MM;
    __half* wh_fc2 = wh + 8 * MM;

    // one conversion launch for ALL weights: 12M floats = 3M float4 -> 12288 blocks
    tohalf_all<<<12 * MM / 4 / 256, 256>>>(wq_w, wk_w, wv_w, wo_w, fc1_w, fc2_w, wh);

    __half* q = qkv;
    __half* k = qkv + (size_t)M_TOK * D_MODEL;
    __half* v = qkv + 2 * (size_t)M_TOK * D_MODEL;

    // --- attention sub-block (pre-norm) ---
    ln_kernel<<<M_TOK, 256>>>(x, ln1_g, ln1_b, h1);
    mma_gemm<3><<<dim3(24, 32), 256, GEMM_SMEM_BYTES>>>(
        h1, wh_qkv, wq_b, wk_b, wv_b, nullptr, qkv, M_TOK, 3 * D_MODEL, D_MODEL);
    attn_tc<<<dim3(SEQ / 128, N_HEADS, BATCH), 128, AT_SMEM>>>(q, k, v, ctx);
    mma_gemm<2><<<dim3(8, 32), 256, GEMM_SMEM_BYTES>>>(
        ctx, wh_o, wo_b, nullptr, nullptr, x, x1, M_TOK, D_MODEL, D_MODEL);

    // --- FFN sub-block (pre-norm) ---
    ln_kernel<<<M_TOK, 256>>>(x1, ln2_g, ln2_b, h2);
    mma_gemm<1><<<dim3(32, 32), 256, GEMM_SMEM_BYTES>>>(
        h2, wh_fc1, fc1_b, nullptr, nullptr, nullptr, ff, M_TOK, D_FF, D_MODEL);
    mma_gemm<2><<<dim3(8, 32), 256, GEMM_SMEM_BYTES>>>(
        ff, wh_fc2, fc2_b, nullptr, nullptr, x1, d_out, M_TOK, D_MODEL, D_FF);
}

// round 10
// speedup vs baseline: 7.7293x; 1.0930x over previous
#include <cuda_runtime.h>
#include <cuda_fp16.h>
#include <math.h>
#include <stdint.h>

#define D_MODEL 1024
#define N_HEADS 16
#define HEAD_DIM 64
#define D_FF     4096
#define BATCH    2
#define SEQ      2048
#define M_TOK    (BATCH*SEQ)   /* 4096 token rows */

// ---------------- scratch (static device globals; no allocation) -------------
__device__ __half g_h1 [M_TOK*D_MODEL];
__device__ __half g_qkv[3*M_TOK*D_MODEL];
__device__ __half g_ctx[M_TOK*D_MODEL];
__device__ __half g_h2 [M_TOK*D_MODEL];
__device__ __half g_ff [M_TOK*D_FF];
__device__ float  g_x1 [M_TOK*D_MODEL];
__device__ __half g_wh [12*1024*1024];   // fp16 weights: q,k,v,o,fc1,fc2

// ---------------- helpers -----------------------------------------------------
__device__ __forceinline__ void mma_f16(float* d, const uint32_t* a, const uint32_t* b) {
    asm volatile(
        "mma.sync.aligned.m16n8k16.row.col.f32.f16.f16.f32 "
        "{%0,%1,%2,%3}, {%4,%5,%6,%7}, {%8,%9}, {%0,%1,%2,%3};"
        : "+f"(d[0]), "+f"(d[1]), "+f"(d[2]), "+f"(d[3])
        : "r"(a[0]), "r"(a[1]), "r"(a[2]), "r"(a[3]), "r"(b[0]), "r"(b[1]));
}
__device__ __forceinline__ void ldsm_x4(uint32_t* r, uint32_t addr) {
    asm volatile("ldmatrix.sync.aligned.m8n8.x4.shared.b16 {%0,%1,%2,%3}, [%4];"
                 : "=r"(r[0]), "=r"(r[1]), "=r"(r[2]), "=r"(r[3]) : "r"(addr));
}
__device__ __forceinline__ void ldsm_x4_t(uint32_t* r, uint32_t addr) {
    asm volatile("ldmatrix.sync.aligned.m8n8.x4.trans.shared.b16 {%0,%1,%2,%3}, [%4];"
                 : "=r"(r[0]), "=r"(r[1]), "=r"(r[2]), "=r"(r[3]) : "r"(addr));
}
__device__ __forceinline__ uint32_t smem_u32(const void* p) {
    uint32_t a;
    asm("{ .reg .u64 t; cvta.to.shared.u64 t, %1; cvt.u32.u64 %0, t; }" : "=r"(a) : "l"(p));
    return a;
}
__device__ __forceinline__ uint32_t packh2(float x, float y) {
    half2 h = __floats2half2_rn(x, y);
    return *(uint32_t*)&h;
}

// ---------------- LayerNorm: warp-per-row, shuffle-only ------------------------
__global__ void __launch_bounds__(256)
ln_kernel(const float* __restrict__ x,
          const float* __restrict__ gamma,
          const float* __restrict__ beta,
          __half* __restrict__ out) {
    const int wid = threadIdx.x >> 5, lane = threadIdx.x & 31;
    const int row = blockIdx.x * 8 + wid;
    const float4* xr = (const float4*)(x + (size_t)row * D_MODEL);
    float4 v[8];
    float s = 0.0f;
    #pragma unroll
    for (int i = 0; i < 8; i++) {
        v[i] = xr[i * 32 + lane];
        s += v[i].x + v[i].y + v[i].z + v[i].w;
    }
    #pragma unroll
    for (int o = 16; o > 0; o >>= 1) s += __shfl_xor_sync(0xFFFFFFFFu, s, o);
    const float mean = s * (1.0f / D_MODEL);
    float s2 = 0.0f;
    #pragma unroll
    for (int i = 0; i < 8; i++) {
        float a = v[i].x - mean, b = v[i].y - mean, c = v[i].z - mean, d = v[i].w - mean;
        s2 += a * a + b * b + c * c + d * d;
    }
    #pragma unroll
    for (int o = 16; o > 0; o >>= 1) s2 += __shfl_xor_sync(0xFFFFFFFFu, s2, o);
    const float rstd = rsqrtf(s2 * (1.0f / D_MODEL) + 1e-5f);
    __half* orow = out + (size_t)row * D_MODEL;
    #pragma unroll
    for (int i = 0; i < 8; i++) {
        const float4 gg = ((const float4*)gamma)[i * 32 + lane];
        const float4 bb = ((const float4*)beta)[i * 32 + lane];
        uint2 o2;
        o2.x = packh2((v[i].x - mean) * rstd * gg.x + bb.x,
                      (v[i].y - mean) * rstd * gg.y + bb.y);
        o2.y = packh2((v[i].z - mean) * rstd * gg.z + bb.z,
                      (v[i].w - mean) * rstd * gg.w + bb.w);
        *(uint2*)(orow + i * 128 + lane * 4) = o2;
    }
}

// ---------------- all-weights -> fp16 conversion (one launch) -----------------
__global__ void tohalf_all(const float* __restrict__ w0, const float* __restrict__ w1,
                           const float* __restrict__ w2, const float* __restrict__ w3,
                           const float* __restrict__ w4, const float* __restrict__ w5,
                           __half* __restrict__ out) {
    const int Q4 = 256 * 1024;           // 1M floats in float4 units
    int i = blockIdx.x * blockDim.x + threadIdx.x;   // float4 index, [0, 3M)
    const float* src; int base;
    if      (i <     Q4) { src = w0; base = 0;      }
    else if (i < 2 * Q4) { src = w1; base = Q4;     }
    else if (i < 3 * Q4) { src = w2; base = 2 * Q4; }
    else if (i < 4 * Q4) { src = w3; base = 3 * Q4; }
    else if (i < 8 * Q4) { src = w4; base = 4 * Q4; }
    else                 { src = w5; base = 8 * Q4; }
    float4 v = ((const float4*)src)[i - base];
    ((half2*)out)[i * 2]     = __floats2half2_rn(v.x, v.y);
    ((half2*)out)[i * 2 + 1] = __floats2half2_rn(v.z, v.w);
}

// ---------------- FP16 mma.sync GEMM:  C[M,N] = A[M,K] @ W[N,K]^T -------------
#define STG_H   (128*40)
#define STAGE_H (2*STG_H)
#define NSTAGE  4
#define GEMM_SMEM_BYTES (NSTAGE*STAGE_H*2 + 512)

__device__ __forceinline__ void load_chunk_h(
    __half* smem_h, const __half* __restrict__ A, const __half* __restrict__ W,
    int bm, int bn, int K, int c, int tid) {
    __half* stage = smem_h + (c & (NSTAGE - 1)) * STAGE_H;
    #pragma unroll
    for (int it = 0; it < 4; it++) {
        int i = tid + it * 256;
        bool isA = i < 512;
        int j = i & 511;
        int row = j >> 2, seg = j & 3;
        __half* dst = stage + (isA ? 0 : STG_H) + row * 40 + seg * 8;
        const __half* src = (isA ? A + (size_t)(bm + row) * K
                                 : W + (size_t)(bn + row) * K) + c * 32 + seg * 8;
        asm volatile("cp.async.cg.shared.global [%0], [%1], 16;"
                     :: "r"(smem_u32(dst)), "l"(src));
    }
    asm volatile("cp.async.commit_group;" ::: "memory");
}

template<int EPI>
__global__ void __launch_bounds__(256, 2)
mma_gemm(const __half* __restrict__ A, const __half* __restrict__ W,
         const float* __restrict__ b0, const float* __restrict__ b1,
         const float* __restrict__ b2, const float* __restrict__ res,
         void* __restrict__ Cv, int M, int N, int K) {
    extern __shared__ char smem[];
    __half* smem_h = (__half*)smem;
    float*  sbias  = (float*)(smem + NSTAGE * STAGE_H * 2);

    const int tid  = threadIdx.x;
    const int wid  = tid >> 5, lane = tid & 31;
    const int wm   = wid >> 2, wn = wid & 3;
    const int bm   = blockIdx.y * 128, bn = blockIdx.x * 128;
    const int NC   = K >> 5;

    const float* bsel = b0;
    int bcol = bn;
    if (EPI == 3) {
        const int which = bn >> 10;
        bsel = (which == 0) ? b0 : (which == 1) ? b1 : b2;
        bcol = bn & 1023;
    }
    if (tid < 128) sbias[tid] = bsel[bcol + tid];

    float acc[4][4][4];
    #pragma unroll
    for (int mt = 0; mt < 4; mt++)
        #pragma unroll
        for (int nt = 0; nt < 4; nt++)
            #pragma unroll
            for (int e = 0; e < 4; e++) acc[mt][nt][e] = 0.0f;

    load_chunk_h(smem_h, A, W, bm, bn, K, 0, tid);
    load_chunk_h(smem_h, A, W, bm, bn, K, 1, tid);
    load_chunk_h(smem_h, A, W, bm, bn, K, 2, tid);

    const int g = lane >> 3, r8 = lane & 7;
    const uint32_t sb = smem_u32(smem_h);
    const uint32_t aBase = sb + ((wm * 64 + (g & 1) * 8 + r8) * 40 + (g >> 1) * 8) * 2;
    const uint32_t bBase = sb + (STG_H + (wn * 32 + (g >> 1) * 8 + r8) * 40 + (g & 1) * 8) * 2;

    for (int c = 0; c < NC; c++) {
        const int rem = NC - 1 - c;
        if (rem >= 2)      asm volatile("cp.async.wait_group 2;" ::: "memory");
        else if (rem == 1) asm volatile("cp.async.wait_group 1;" ::: "memory");
        else               asm volatile("cp.async.wait_group 0;" ::: "memory");
        __syncthreads();

        if (c + 3 < NC) load_chunk_h(smem_h, A, W, bm, bn, K, c + 3, tid);

        const uint32_t stOff = (uint32_t)(c & (NSTAGE - 1)) * (STAGE_H * 2);
        #pragma unroll
        for (int ks = 0; ks < 2; ks++) {
            uint32_t a[4][4], b[2][4];
            #pragma unroll
            for (int mt = 0; mt < 4; mt++)
                ldsm_x4(a[mt], aBase + stOff + mt * (16 * 40 * 2) + ks * 32);
            #pragma unroll
            for (int ntp = 0; ntp < 2; ntp++)
                ldsm_x4(b[ntp], bBase + stOff + ntp * (16 * 40 * 2) + ks * 32);
            #pragma unroll
            for (int mt = 0; mt < 4; mt++)
                #pragma unroll
                for (int nt = 0; nt < 4; nt++)
                    mma_f16(acc[mt][nt], a[mt], &b[nt >> 1][(nt & 1) * 2]);
        }
    }

    const int lr4 = lane >> 2, lc = lane & 3;
    const int cstride = (EPI == 3) ? 1024 : N;
    __half* Ch = (__half*)Cv;
    if (EPI == 3) Ch += (size_t)(bn >> 10) * M_TOK * 1024;
    const int cbn = (EPI == 3) ? (bn & 1023) : bn;

    #pragma unroll
    for (int mt = 0; mt < 4; mt++) {
        const int row0 = bm + wm * 64 + mt * 16 + lr4;
        #pragma unroll
        for (int nt = 0; nt < 4; nt++) {
            const int coll = wn * 32 + nt * 8 + lc * 2;
            const int col  = cbn + coll;
            #pragma unroll
            for (int half_i = 0; half_i < 2; half_i++) {
                const int row = row0 + half_i * 8;
                float ox = acc[mt][nt][half_i * 2 + 0] + sbias[coll];
                float oy = acc[mt][nt][half_i * 2 + 1] + sbias[coll + 1];
                if (EPI == 0 || EPI == 3) {
                    *(half2*)(Ch + (size_t)row * cstride + col) = __floats2half2_rn(ox, oy);
                } else if (EPI == 1) {
                    ox = 0.5f * ox * (1.0f + erff(ox * 0.70710678118654752f));
                    oy = 0.5f * oy * (1.0f + erff(oy * 0.70710678118654752f));
                    *(half2*)(Ch + (size_t)row * cstride + col) = __floats2half2_rn(ox, oy);
                } else {
                    const float2 rv = *(const float2*)(res + (size_t)row * N + col);
                    float2 o; o.x = ox + rv.x; o.y = oy + rv.y;
                    *(float2*)((float*)Cv + (size_t)row * N + col) = o;
                }
            }
        }
    }
}

// ---------------- Tensor-core causal flash attention (fp16, FA2-style) --------
// CTA: 128 queries x 1 head, 256 threads (8 warps x 16 q-rows).
// K/V raw tiles double-buffered via cp.async; V consumed via ldmatrix.trans;
// P stays in registers (S-accumulator fragment == A-fragment for P@V).
#define ATS 72
#define AT_TILE (64*ATS)
#define AT_SMEM ((128*ATS + 4*AT_TILE)*2)

__device__ __forceinline__ void at_prefetch(
    __half* Ks, __half* Vs, const __half* __restrict__ K, const __half* __restrict__ V,
    size_t kbase, int st, int tid) {
    __half* kd = Ks + st * AT_TILE;
    __half* vd = Vs + st * AT_TILE;
    #pragma unroll
    for (int it = 0; it < 2; it++) {
        const int i = tid + it * 256;      // 0..511
        const int row = i >> 3, seg = i & 7;
        const size_t go = kbase + (size_t)row * D_MODEL + seg * 8;
        asm volatile("cp.async.cg.shared.global [%0], [%1], 16;"
                     :: "r"(smem_u32(kd + row * ATS + seg * 8)), "l"(K + go));
        asm volatile("cp.async.cg.shared.global [%0], [%1], 16;"
                     :: "r"(smem_u32(vd + row * ATS + seg * 8)), "l"(V + go));
    }
    asm volatile("cp.async.commit_group;" ::: "memory");
}

__global__ void __launch_bounds__(256, 2)
attn_tc(const __half* __restrict__ Q, const __half* __restrict__ K,
        const __half* __restrict__ V, __half* __restrict__ O) {
    extern __shared__ __half smh[];
    __half* Qs = smh;                      // [128][72]
    __half* Ks = Qs + 128 * ATS;           // 2 x [64][72]
    __half* Vs = Ks + 2 * AT_TILE;         // 2 x [64][72] (raw [tok][d])
    const int tid = threadIdx.x;
    const int wid = tid >> 5, lane = tid & 31;
    const int g = lane >> 3, r8 = lane & 7;
    const int lr4 = lane >> 2, lc = lane & 3;

    const int qb = (gridDim.x - 1) - blockIdx.x;   // heavy tiles first
    const int h = blockIdx.y, b = blockIdx.z;
    const size_t qbase = ((size_t)(b * SEQ + qb * 128) * D_MODEL) + h * HEAD_DIM;
    const size_t kvbase0 = ((size_t)(b * SEQ) * D_MODEL) + h * HEAD_DIM;

    // prefetch tile 0
    at_prefetch(Ks, Vs, K, V, kvbase0, 0, tid);

    // load Q tile (scaled by 1/8)
    const half2 scl = __half2half2(__float2half(0.125f));
    #pragma unroll
    for (int it = 0; it < 4; it++) {
        const int i = tid + it * 256;
        const int row = i >> 3, seg = i & 7;
        const half2* src = (const half2*)(Q + qbase + (size_t)row * D_MODEL + seg * 8);
        half2* dst = (half2*)(Qs + row * ATS + seg * 8);
        #pragma unroll
        for (int j = 0; j < 4; j++) dst[j] = __hmul2(src[j], scl);
    }

    float m[2], l[2], acc[8][4];
    m[0] = m[1] = -1e30f; l[0] = l[1] = 0.0f;
    #pragma unroll
    for (int nt = 0; nt < 8; nt++)
        #pragma unroll
        for (int e = 0; e < 4; e++) acc[nt][e] = 0.0f;

    // per-warp/lane ldmatrix bases (stage-relative byte offsets added later)
    const uint32_t qA = smem_u32(Qs) + ((wid * 16 + (g & 1) * 8 + r8) * ATS + (g >> 1) * 8) * 2;
    const uint32_t kB0 = smem_u32(Ks) + (((g >> 1) * 8 + r8) * ATS + (g & 1) * 8) * 2;
    const uint32_t vB0 = smem_u32(Vs) + (((g & 1) * 8 + r8) * ATS + (g >> 1) * 8) * 2;

    const int ntk = 2 * qb + 2;
    for (int kt = 0; kt < ntk; kt++) {
        if (kt + 1 < ntk)
            at_prefetch(Ks, Vs, K, V, kvbase0 + (size_t)(kt + 1) * 64 * D_MODEL, (kt + 1) & 1, tid);
        if (kt + 1 < ntk) asm volatile("cp.async.wait_group 1;" ::: "memory");
        else              asm volatile("cp.async.wait_group 0;" ::: "memory");
        __syncthreads();

        const uint32_t stB = (uint32_t)(kt & 1) * (AT_TILE * 2);
        const uint32_t kB = kB0 + stB, vB = vB0 + stB;

        // ---- S = Q @ K^T ----
        float s[8][4];
        #pragma unroll
        for (int nt = 0; nt < 8; nt++)
            #pragma unroll
            for (int e = 0; e < 4; e++) s[nt][e] = 0.0f;

        #pragma unroll
        for (int ks = 0; ks < 4; ks++) {
            uint32_t aQ[4];
            ldsm_x4(aQ, qA + ks * 32);
            #pragma unroll
            for (int j = 0; j < 4; j++) {
                uint32_t bb[4];
                ldsm_x4(bb, kB + j * (16 * ATS * 2) + ks * 32);
                mma_f16(s[2 * j],     aQ, bb);
                mma_f16(s[2 * j + 1], aQ, bb + 2);
            }
        }

        // causal mask (diagonal-region tiles only)
        if (kt >= 2 * qb) {
            const int row0 = qb * 128 + wid * 16 + lr4;
            #pragma unroll
            for (int nt = 0; nt < 8; nt++) {
                const int col0 = kt * 64 + nt * 8 + 2 * lc;
                if (col0     > row0)     s[nt][0] = -1e9f;
                if (col0 + 1 > row0)     s[nt][1] = -1e9f;
                if (col0     > row0 + 8) s[nt][2] = -1e9f;
                if (col0 + 1 > row0 + 8) s[nt][3] = -1e9f;
            }
        }

        // ---- online softmax (fp32, quad shuffles) ----
        #pragma unroll
        for (int hf = 0; hf < 2; hf++) {
            float mx = m[hf];
            #pragma unroll
            for (int nt = 0; nt < 8; nt++)
                mx = fmaxf(mx, fmaxf(s[nt][hf * 2], s[nt][hf * 2 + 1]));
            mx = fmaxf(mx, __shfl_xor_sync(0xFFFFFFFFu, mx, 1));
            mx = fmaxf(mx, __shfl_xor_sync(0xFFFFFFFFu, mx, 2));
            const float corr = __expf(m[hf] - mx);
            m[hf] = mx;
            float sum = 0.0f;
            #pragma unroll
            for (int nt = 0; nt < 8; nt++) {
                float p0 = __expf(s[nt][hf * 2]     - mx);
                float p1 = __expf(s[nt][hf * 2 + 1] - mx);
                s[nt][hf * 2] = p0; s[nt][hf * 2 + 1] = p1;
                sum += p0 + p1;
            }
            sum += __shfl_xor_sync(0xFFFFFFFFu, sum, 1);
            sum += __shfl_xor_sync(0xFFFFFFFFu, sum, 2);
            l[hf] = l[hf] * corr + sum;
            #pragma unroll
            for (int nt = 0; nt < 8; nt++) {
                acc[nt][hf * 2]     *= corr;
                acc[nt][hf * 2 + 1] *= corr;
            }
        }

        // ---- O += P @ V  (P stays in registers; V via ldmatrix.trans) ----
        #pragma unroll
        for (int ks = 0; ks < 4; ks++) {
            uint32_t aP[4];
            aP[0] = packh2(s[2 * ks][0],     s[2 * ks][1]);
            aP[1] = packh2(s[2 * ks][2],     s[2 * ks][3]);
            aP[2] = packh2(s[2 * ks + 1][0], s[2 * ks + 1][1]);
            aP[3] = packh2(s[2 * ks + 1][2], s[2 * ks + 1][3]);
            #pragma unroll
            for (int j = 0; j < 4; j++) {
                uint32_t bb[4];
                ldsm_x4_t(bb, vB + ks * (16 * ATS * 2) + j * 32);
                mma_f16(acc[2 * j],     aP, bb);
                mma_f16(acc[2 * j + 1], aP, bb + 2);
            }
        }
        __syncthreads();   // all warps done with stage kt&1 before it is overwritten
    }

    // ---- epilogue: O = acc / l (fp16 out, feeds Wo GEMM) ----
    const float inv0 = 1.0f / l[0], inv1 = 1.0f / l[1];
    const int row0 = qb * 128 + wid * 16 + lr4;
    #pragma unroll
    for (int nt = 0; nt < 8; nt++) {
        const int col = h * HEAD_DIM + nt * 8 + 2 * lc;
        *(half2*)(O + (size_t)(b * SEQ + row0) * D_MODEL + col) =
            __floats2half2_rn(acc[nt][0] * inv0, acc[nt][1] * inv0);
        *(half2*)(O + (size_t)(b * SEQ + row0 + 8) * D_MODEL + col) =
            __floats2half2_rn(acc[nt][2] * inv1, acc[nt][3] * inv1);
    }
}

// ---------------- launch ------------------------------------------------------
extern "C" void kernel_launch(void* const* d_in, const int* in_sizes, int n_in,
                              void* d_out, int out_size) {
    const float* x     = (const float*)d_in[0];
    const float* wq_w  = (const float*)d_in[2];
    const float* wq_b  = (const float*)d_in[3];
    const float* wk_w  = (const float*)d_in[4];
    const float* wk_b  = (const float*)d_in[5];
    const float* wv_w  = (const float*)d_in[6];
    const float* wv_b  = (const float*)d_in[7];
    const float* wo_w  = (const float*)d_in[8];
    const float* wo_b  = (const float*)d_in[9];
    const float* fc1_w = (const float*)d_in[10];
    const float* fc1_b = (const float*)d_in[11];
    const float* fc2_w = (const float*)d_in[12];
    const float* fc2_b = (const float*)d_in[13];
    const float* ln1_g = (const float*)d_in[14];
    const float* ln1_b = (const float*)d_in[15];
    const float* ln2_g = (const float*)d_in[16];
    const float* ln2_b = (const float*)d_in[17];

    __half *h1, *qkv, *ctx, *h2, *ff, *wh;
    float *x1;
    cudaGetSymbolAddress((void**)&h1,  g_h1);
    cudaGetSymbolAddress((void**)&qkv, g_qkv);
    cudaGetSymbolAddress((void**)&ctx, g_ctx);
    cudaGetSymbolAddress((void**)&h2,  g_h2);
    cudaGetSymbolAddress((void**)&ff,  g_ff);
    cudaGetSymbolAddress((void**)&x1,  g_x1);
    cudaGetSymbolAddress((void**)&wh,  g_wh);

    cudaFuncSetAttribute(mma_gemm<1>, cudaFuncAttributeMaxDynamicSharedMemorySize, GEMM_SMEM_BYTES);
    cudaFuncSetAttribute(mma_gemm<2>, cudaFuncAttributeMaxDynamicSharedMemorySize, GEMM_SMEM_BYTES);
    cudaFuncSetAttribute(mma_gemm<3>, cudaFuncAttributeMaxDynamicSharedMemorySize, GEMM_SMEM_BYTES);
    cudaFuncSetAttribute(attn_tc,     cudaFuncAttributeMaxDynamicSharedMemorySize, AT_SMEM);

    const int MM = 1024 * 1024;
    __half* wh_qkv = wh;
    __half* wh_o   = wh + 3 * MM;
    __half* wh_fc1 = wh + 4 * MM;
    __half* wh_fc2 = wh + 8 * MM;

    tohalf_all<<<12 * MM / 4 / 256, 256>>>(wq_w, wk_w, wv_w, wo_w, fc1_w, fc2_w, wh);

    __half* q = qkv;
    __half* k = qkv + (size_t)M_TOK * D_MODEL;
    __half* v = qkv + 2 * (size_t)M_TOK * D_MODEL;

    // --- attention sub-block (pre-norm) ---
    ln_kernel<<<M_TOK / 8, 256>>>(x, ln1_g, ln1_b, h1);
    mma_gemm<3><<<dim3(24, 32), 256, GEMM_SMEM_BYTES>>>(
        h1, wh_qkv, wq_b, wk_b, wv_b, nullptr, qkv, M_TOK, 3 * D_MODEL, D_MODEL);
    attn_tc<<<dim3(SEQ / 128, N_HEADS, BATCH), 256, AT_SMEM>>>(q, k, v, ctx);
    mma_gemm<2><<<dim3(8, 32), 256, GEMM_SMEM_BYTES>>>(
        ctx, wh_o, wo_b, nullptr, nullptr, x, x1, M_TOK, D_MODEL, D_MODEL);

    // --- FFN sub-block (pre-norm) ---
    ln_kernel<<<M_TOK / 8, 256>>>(x1, ln2_g, ln2_b, h2);
    mma_gemm<1><<<dim3(32, 32), 256, GEMM_SMEM_BYTES>>>(
        h2, wh_fc1, fc1_b, nullptr, nullptr, nullptr, ff, M_TOK, D_FF, D_MODEL);
    mma_gemm<2><<<dim3(8, 32), 256, GEMM_SMEM_BYTES>>>(
        ff, wh_fc2, fc2_b, nullptr, nullptr, x1, d_out, M_TOK, D_MODEL, D_FF);
}